// round 1
// baseline (speedup 1.0000x reference)
#include <cuda_runtime.h>
#include <math.h>

#define B_     2
#define S_     2048
#define D_     2048
#define NQ_    16
#define NKV_   8
#define H_     256
#define WINDOW_ 1024

// ---------------------------------------------------------------------------
// Scratch (static device globals; no allocation anywhere)
// ---------------------------------------------------------------------------
__device__ float g_q [B_*S_*NQ_ *H_];   // 64 MB  [b][t][n][h]
__device__ float g_k [B_*S_*NKV_*H_];   // 32 MB  [b][t][k][h]
__device__ float g_v [B_*S_*NKV_*H_];   // 32 MB  [b][t][k][h]
__device__ float g_av[B_*S_*NQ_ *H_];   // 64 MB  [b][t][n][h]

// ---------------------------------------------------------------------------
// Generic 64x64x16-tiled SGEMM, 4x4 register microtile, 256 threads.
// C[m][z*cStride + bx*64 + n] = sum_k A[m][k] * B[z*bStride + k*ldb + ...]
// grid = (N/64, M/64, nBatch)
// ---------------------------------------------------------------------------
__global__ void __launch_bounds__(256) gemm64_kernel(
    const float* __restrict__ A, const float* __restrict__ Bm, float* __restrict__ C,
    int K, int lda, int ldb, int ldc, long long bStride, int cStride)
{
    __shared__ float As[16][68];   // transposed A tile [k][m]
    __shared__ float Bs[16][64];   // natural   B tile [k][n]

    const int tid = threadIdx.x;
    const int tx  = tid & 15;
    const int ty  = tid >> 4;
    const int m0  = blockIdx.y * 64;
    const int z   = blockIdx.z;
    const int nb  = blockIdx.x * 64;

    const float* Bp    = Bm + (long long)z * bStride;
    const int    cbase = z * cStride + nb;

    const int ar = tid >> 2;        // 0..63  (A tile row)
    const int ac = (tid & 3) * 4;   // 0,4,8,12
    const int bk = tid >> 4;        // 0..15  (B tile k-row)
    const int bc = (tid & 15) * 4;  // 0..60

    const float* Aptr = A  + (long long)(m0 + ar) * lda + ac;
    const float* Bptr = Bp + (long long)bk * ldb + nb + bc;

    float acc[4][4];
#pragma unroll
    for (int i = 0; i < 4; i++)
#pragma unroll
        for (int j = 0; j < 4; j++) acc[i][j] = 0.f;

    for (int k0 = 0; k0 < K; k0 += 16) {
        float4 avv = *(const float4*)(Aptr + k0);
        float4 bvv = *(const float4*)(Bptr + (long long)k0 * ldb);
        As[ac + 0][ar] = avv.x;
        As[ac + 1][ar] = avv.y;
        As[ac + 2][ar] = avv.z;
        As[ac + 3][ar] = avv.w;
        *(float4*)&Bs[bk][bc] = bvv;
        __syncthreads();
#pragma unroll
        for (int kk = 0; kk < 16; kk++) {
            float4 a4 = *(const float4*)&As[kk][ty * 4];
            float4 b4 = *(const float4*)&Bs[kk][tx * 4];
            float a[4] = {a4.x, a4.y, a4.z, a4.w};
            float b[4] = {b4.x, b4.y, b4.z, b4.w};
#pragma unroll
            for (int i = 0; i < 4; i++)
#pragma unroll
                for (int j = 0; j < 4; j++) acc[i][j] = fmaf(a[i], b[j], acc[i][j]);
        }
        __syncthreads();
    }

#pragma unroll
    for (int i = 0; i < 4; i++) {
        float4 r = make_float4(acc[i][0], acc[i][1], acc[i][2], acc[i][3]);
        *(float4*)(C + (long long)(m0 + ty * 4 + i) * ldc + cbase + tx * 4) = r;
    }
}

// ---------------------------------------------------------------------------
// RoPE (interleaved output layout, matching jnp.stack([r1,r2],-1).reshape)
// One block of 128 threads per (b,t,head) row. scale applied after rotation.
// ---------------------------------------------------------------------------
__global__ void rope_kernel(float* __restrict__ data, int nheads, float scale)
{
    long long bid = blockIdx.x;                 // (b*S + t)*nheads + n
    int t = (int)((bid / nheads) % S_);
    int i = threadIdx.x;                        // 0..127
    float* p = data + bid * H_;

    float x1 = p[i];
    float x2 = p[i + 128];

    float ex       = (float)(2 * i) * (1.0f / (float)H_);
    float inv_freq = powf(10000.0f, -ex);
    float ff       = (float)t * inv_freq;       // same fp32 product as reference
    // exact range reduction of the fp32 freq, then fp32 trig
    double fr = (double)ff;
    const double TWO_PI = 6.283185307179586476925286766559;
    fr = fr - floor(fr / TWO_PI) * TWO_PI;
    float c = cosf((float)fr);
    float s = sinf((float)fr);

    __syncthreads();
    p[2 * i]     = (x1 * c - x2 * s) * scale;
    p[2 * i + 1] = (x2 * c + x1 * s) * scale;
}

// ---------------------------------------------------------------------------
// Flash-style sliding-window causal attention with tanh soft-cap.
// Block = 256 threads, one (b, qhead, 64-query tile).
// smem: Qs^T [256][64], Ks^T [256][64], Vs [64][256], Ps^T [64][68]
// ---------------------------------------------------------------------------
#define ATTN_SMEM_FLOATS (3 * 256 * 64 + 64 * 68)
#define ATTN_SMEM_BYTES  (ATTN_SMEM_FLOATS * 4)

__global__ void __launch_bounds__(256, 1) attn_kernel()
{
    extern __shared__ float sm[];
    float* Qs = sm;                 // [h][row]   stride 64
    float* Ks = sm + 256 * 64;      // [h][col]   stride 64
    float* Vs = sm + 2 * 256 * 64;  // [row][h]   stride 256
    float* Ps = sm + 3 * 256 * 64;  // [col][row] stride 68

    const int tid = threadIdx.x;
    const int tx  = tid & 15;
    const int ty  = tid >> 4;
    const int qt0 = blockIdx.x * 64;
    const int bn  = blockIdx.y;
    const int b   = bn / NQ_;
    const int n   = bn % NQ_;
    const int kvh = n >> 1;         // G = 2

    // ---- load Q tile transposed: [h][row] ----
    {
        int s = tid & 63;
        int hg0 = tid >> 6;         // 0..3
        const float* qb = g_q + (((long long)(b * S_) + qt0 + s) * NQ_ + n) * H_;
#pragma unroll
        for (int it = 0; it < 16; it++) {
            int hg = hg0 + it * 4;  // 0..63
            float4 v = *(const float4*)(qb + hg * 4);
            Qs[(hg * 4 + 0) * 64 + s] = v.x;
            Qs[(hg * 4 + 1) * 64 + s] = v.y;
            Qs[(hg * 4 + 2) * 64 + s] = v.z;
            Qs[(hg * 4 + 3) * 64 + s] = v.w;
        }
    }

    float o[4][16];
#pragma unroll
    for (int i = 0; i < 4; i++)
#pragma unroll
        for (int c = 0; c < 16; c++) o[i][c] = 0.f;

    float m_i[4], l_i[4];
#pragma unroll
    for (int i = 0; i < 4; i++) { m_i[i] = -1e30f; l_i[i] = 0.f; }

    int lo = qt0 - (WINDOW_ - 1); if (lo < 0) lo = 0;
    const int kt_lo = lo >> 6;
    const int kt_hi = blockIdx.x;

    const float* kbase = g_k + ((long long)(b * S_) * NKV_ + kvh) * H_;
    const float* vbase = g_v + ((long long)(b * S_) * NKV_ + kvh) * H_;

    for (int kt = kt_lo; kt <= kt_hi; kt++) {
        const int kt0 = kt << 6;
        __syncthreads();   // previous PV done; also orders first-iter Q load

        // ---- load K tile transposed [h][col] ----
        {
            int s = tid & 63;
            int hg0 = tid >> 6;
            const float* kb = kbase + (long long)(kt0 + s) * (NKV_ * H_);
#pragma unroll
            for (int it = 0; it < 16; it++) {
                int hg = hg0 + it * 4;
                float4 v = *(const float4*)(kb + hg * 4);
                Ks[(hg * 4 + 0) * 64 + s] = v.x;
                Ks[(hg * 4 + 1) * 64 + s] = v.y;
                Ks[(hg * 4 + 2) * 64 + s] = v.z;
                Ks[(hg * 4 + 3) * 64 + s] = v.w;
            }
        }
        // ---- load V tile natural [row][h] (fully coalesced) ----
        {
#pragma unroll
            for (int it = 0; it < 16; it++) {
                int idx = it * 256 + tid;
                int s = idx >> 6, hg = idx & 63;
                float4 v = *(const float4*)(vbase + (long long)(kt0 + s) * (NKV_ * H_) + hg * 4);
                *(float4*)&Vs[s * 256 + hg * 4] = v;
            }
        }
        __syncthreads();

        // ---- S = Q K^T (64x64, k=256) ----
        float acc[4][4];
#pragma unroll
        for (int i = 0; i < 4; i++)
#pragma unroll
            for (int j = 0; j < 4; j++) acc[i][j] = 0.f;

#pragma unroll 8
        for (int h = 0; h < 256; h++) {
            float4 q4 = *(const float4*)&Qs[h * 64 + ty * 4];
            float4 k4 = *(const float4*)&Ks[h * 64 + tx * 4];
            float qa[4] = {q4.x, q4.y, q4.z, q4.w};
            float ka[4] = {k4.x, k4.y, k4.z, k4.w};
#pragma unroll
            for (int i = 0; i < 4; i++)
#pragma unroll
                for (int j = 0; j < 4; j++) acc[i][j] = fmaf(qa[i], ka[j], acc[i][j]);
        }

        // ---- soft-cap + sliding-window causal mask ----
        float rmax[4] = {-1e30f, -1e30f, -1e30f, -1e30f};
#pragma unroll
        for (int i = 0; i < 4; i++) {
            const int tg = qt0 + ty * 4 + i;
#pragma unroll
            for (int j = 0; j < 4; j++) {
                const int sg = kt0 + tx * 4 + j;
                float xv = acc[i][j] * 0.02f;                       // /50
                xv = fminf(fmaxf(xv, -15.f), 15.f);
                float e  = __expf(2.f * xv);
                float lv = 50.f * (e - 1.f) / (e + 1.f);            // 50*tanh
                if (sg > tg || sg <= tg - WINDOW_) lv = -1e30f;
                acc[i][j] = lv;
                rmax[i] = fmaxf(rmax[i], lv);
            }
        }
#pragma unroll
        for (int i = 0; i < 4; i++) {
            rmax[i] = fmaxf(rmax[i], __shfl_xor_sync(0xffffffffu, rmax[i], 8, 16));
            rmax[i] = fmaxf(rmax[i], __shfl_xor_sync(0xffffffffu, rmax[i], 4, 16));
            rmax[i] = fmaxf(rmax[i], __shfl_xor_sync(0xffffffffu, rmax[i], 2, 16));
            rmax[i] = fmaxf(rmax[i], __shfl_xor_sync(0xffffffffu, rmax[i], 1, 16));
        }
        float alpha[4], rsum[4] = {0.f, 0.f, 0.f, 0.f};
#pragma unroll
        for (int i = 0; i < 4; i++) {
            float mn = fmaxf(m_i[i], rmax[i]);
            alpha[i] = __expf(m_i[i] - mn);
            m_i[i] = mn;
        }
#pragma unroll
        for (int i = 0; i < 4; i++)
#pragma unroll
            for (int j = 0; j < 4; j++) {
                float p = (acc[i][j] > -1e29f) ? __expf(acc[i][j] - m_i[i]) : 0.f;
                acc[i][j] = p;
                rsum[i] += p;
            }
#pragma unroll
        for (int i = 0; i < 4; i++) {
            rsum[i] += __shfl_xor_sync(0xffffffffu, rsum[i], 8, 16);
            rsum[i] += __shfl_xor_sync(0xffffffffu, rsum[i], 4, 16);
            rsum[i] += __shfl_xor_sync(0xffffffffu, rsum[i], 2, 16);
            rsum[i] += __shfl_xor_sync(0xffffffffu, rsum[i], 1, 16);
            l_i[i] = l_i[i] * alpha[i] + rsum[i];
        }
#pragma unroll
        for (int i = 0; i < 4; i++)
#pragma unroll
            for (int c = 0; c < 16; c++) o[i][c] *= alpha[i];

        // ---- stage P transposed [col][row] ----
#pragma unroll
        for (int i = 0; i < 4; i++)
#pragma unroll
            for (int j = 0; j < 4; j++)
                Ps[(tx * 4 + j) * 68 + ty * 4 + i] = acc[i][j];
        __syncthreads();

        // ---- O += P V (64x256, k=64) ----
#pragma unroll 4
        for (int j = 0; j < 64; j++) {
            float4 p4 = *(const float4*)&Ps[j * 68 + ty * 4];
            float pr[4] = {p4.x, p4.y, p4.z, p4.w};
#pragma unroll
            for (int c4 = 0; c4 < 4; c4++) {
                float4 v4 = *(const float4*)&Vs[j * 256 + tx * 16 + c4 * 4];
#pragma unroll
                for (int i = 0; i < 4; i++) {
                    o[i][c4 * 4 + 0] = fmaf(pr[i], v4.x, o[i][c4 * 4 + 0]);
                    o[i][c4 * 4 + 1] = fmaf(pr[i], v4.y, o[i][c4 * 4 + 1]);
                    o[i][c4 * 4 + 2] = fmaf(pr[i], v4.z, o[i][c4 * 4 + 2]);
                    o[i][c4 * 4 + 3] = fmaf(pr[i], v4.w, o[i][c4 * 4 + 3]);
                }
            }
        }
    }

    // ---- normalize + write av ----
#pragma unroll
    for (int i = 0; i < 4; i++) {
        float inv = 1.0f / l_i[i];
        long long row = ((long long)(b * S_) + qt0 + ty * 4 + i) * NQ_ + n;
        float* op = g_av + row * H_ + tx * 16;
#pragma unroll
        for (int c4 = 0; c4 < 4; c4++) {
            float4 w = make_float4(o[i][c4 * 4 + 0] * inv, o[i][c4 * 4 + 1] * inv,
                                   o[i][c4 * 4 + 2] * inv, o[i][c4 * 4 + 3] * inv);
            *(float4*)(op + c4 * 4) = w;
        }
    }
}

// ---------------------------------------------------------------------------
// Launch
// ---------------------------------------------------------------------------
extern "C" void kernel_launch(void* const* d_in, const int* in_sizes, int n_in,
                              void* d_out, int out_size)
{
    const float* x  = (const float*)d_in[0];
    const float* Wq = (const float*)d_in[1];
    const float* Wk = (const float*)d_in[2];
    const float* Wv = (const float*)d_in[3];
    const float* Wo = (const float*)d_in[4];
    float* out = (float*)d_out;

    float *q, *k, *v, *av;
    cudaGetSymbolAddress((void**)&q,  g_q);
    cudaGetSymbolAddress((void**)&k,  g_k);
    cudaGetSymbolAddress((void**)&v,  g_v);
    cudaGetSymbolAddress((void**)&av, g_av);

    const int M = B_ * S_;      // 4096
    dim3 blk(256);

    // QKV projections: per-head GEMM 4096 x 256 x 2048
    gemm64_kernel<<<dim3(H_ / 64, M / 64, NQ_),  blk>>>(x, Wq, q, D_, D_, H_, NQ_ * H_, (long long)D_ * H_, H_);
    gemm64_kernel<<<dim3(H_ / 64, M / 64, NKV_), blk>>>(x, Wk, k, D_, D_, H_, NKV_ * H_, (long long)D_ * H_, H_);
    gemm64_kernel<<<dim3(H_ / 64, M / 64, NKV_), blk>>>(x, Wv, v, D_, D_, H_, NKV_ * H_, (long long)D_ * H_, H_);

    // RoPE (q also scaled by 1/sqrt(H)=1/16)
    rope_kernel<<<M * NQ_,  128>>>(q, NQ_,  0.0625f);
    rope_kernel<<<M * NKV_, 128>>>(k, NKV_, 1.0f);

    // Attention
    cudaFuncSetAttribute(attn_kernel, cudaFuncAttributeMaxDynamicSharedMemorySize, ATTN_SMEM_BYTES);
    attn_kernel<<<dim3(S_ / 64, B_ * NQ_), blk, ATTN_SMEM_BYTES>>>();

    // Output projection: 4096 x 2048 x 4096
    gemm64_kernel<<<dim3(D_ / 64, M / 64, 1), blk>>>(av, Wo, out, NQ_ * H_, NQ_ * H_, D_, D_, 0, 0);
}

// round 3
// speedup vs baseline: 1.0505x; 1.0505x over previous
#include <cuda_runtime.h>
#include <cuda_fp16.h>
#include <cstdint>
#include <math.h>

#define B_     2
#define S_     2048
#define D_     2048
#define NQ_    16
#define NKV_   8
#define H_     256
#define WINDOW_ 1024

// ---------------------------------------------------------------------------
// Scratch (static device globals; no allocation anywhere)
// ---------------------------------------------------------------------------
__device__ float g_q [B_*S_*NQ_ *H_];   // 64 MB  [b][t][n][h]
__device__ float g_k [B_*S_*NKV_*H_];   // 32 MB  [b][t][k][h]
__device__ float g_v [B_*S_*NKV_*H_];   // 32 MB  [b][t][k][h]
__device__ float g_av[B_*S_*NQ_ *H_];   // 64 MB  [b][t][n][h]

// ===========================================================================
// mma.sync fp16x3 GEMM: C[M,N] = A[M,K] * B[K,N]   (B stored [K][N] row-major)
// Split a = ah + al (fp16), D += Ah*Bh + Al*Bh + Ah*Bl  (fp32 accumulate)
// Tile 128x128x32, 256 threads = 8 warps (4 M x 2 N), warp tile 32x64.
// smem: Ahi/Alo [128][40] fp16, Bhi/Blo [128 n][40 k] fp16, double buffered.
// ===========================================================================
#define GLDA 40
#define GLDB 40
#define OFF_AHI 0
#define OFF_ALO (128*GLDA)            // halves
#define OFF_BHI (2*128*GLDA)
#define OFF_BLO (2*128*GLDA + 128*GLDB)
#define BUF_HALVES (2*128*GLDA + 2*128*GLDB)   // 20480 halves = 40960 B
#define GEMM_SMEM_BYTES (2 * BUF_HALVES * 2)   // 81920 B

#define MMA16816(c, a, b0, b1)                                               \
    asm volatile("mma.sync.aligned.m16n8k16.row.col.f32.f16.f16.f32 "        \
        "{%0,%1,%2,%3}, {%4,%5,%6,%7}, {%8,%9}, {%0,%1,%2,%3};"              \
        : "+f"((c)[0]), "+f"((c)[1]), "+f"((c)[2]), "+f"((c)[3])             \
        : "r"((a)[0]), "r"((a)[1]), "r"((a)[2]), "r"((a)[3]),                \
          "r"(b0), "r"(b1))

__global__ void __launch_bounds__(256, 1)
mma_gemm_kernel(const float* __restrict__ A, int lda,
                const float* __restrict__ Bw, int ldb, long long bZStride,
                float* __restrict__ C, int ldc, int cZStride, int K)
{
    extern __shared__ __half sh[];

    const int tid  = threadIdx.x;
    const int wid  = tid >> 5;
    const int lane = tid & 31;
    const int gid  = lane >> 2;        // 0..7
    const int tid2 = (lane & 3) * 2;   // 0,2,4,6

    const int warpM = wid & 3;         // 0..3  -> m offset 32*warpM
    const int warpN = wid >> 2;        // 0..1  -> n offset 64*warpN

    const int m0 = blockIdx.y * 128;
    const int n0 = blockIdx.x * 128;
    const int z  = blockIdx.z;
    const float* Bp = Bw + (long long)z * bZStride;

    float acc[2][8][4];
#pragma unroll
    for (int mt = 0; mt < 2; mt++)
#pragma unroll
        for (int nf = 0; nf < 8; nf++)
#pragma unroll
            for (int r = 0; r < 4; r++) acc[mt][nf][r] = 0.f;

    const int nSlab = K >> 5;

    // prefetch register staging
    float4 ra[4], rb[4];

    // A loader indices: lin = p*256+tid, row = lin>>3, k4 = (lin&7)*4
    const int a_row = tid >> 3;          // + p*32
    const int a_k4  = (tid & 7) * 4;
    // B loader indices: lin = p*256+tid, kk = lin>>5, n4 = (lin&31)*4
    const int b_kk  = tid >> 5;          // + p*8
    const int b_n4  = (tid & 31) * 4;

#define LOAD_REGS(s) do {                                                     \
    const int k0 = (s) << 5;                                                  \
    _Pragma("unroll")                                                         \
    for (int p = 0; p < 4; p++)                                               \
        ra[p] = *(const float4*)(A + (long long)(m0 + a_row + p * 32) * lda + k0 + a_k4); \
    _Pragma("unroll")                                                         \
    for (int p = 0; p < 4; p++)                                               \
        rb[p] = *(const float4*)(Bp + (long long)(k0 + b_kk + p * 8) * ldb + n0 + b_n4);  \
} while (0)

#define STORE_SMEM(buf) do {                                                  \
    __half* base = sh + (buf) * BUF_HALVES;                                   \
    _Pragma("unroll")                                                         \
    for (int p = 0; p < 4; p++) {                                             \
        float xs[4] = {ra[p].x, ra[p].y, ra[p].z, ra[p].w};                   \
        const int row = a_row + p * 32;                                       \
        _Pragma("unroll")                                                     \
        for (int j = 0; j < 4; j++) {                                         \
            __half h = __float2half_rn(xs[j]);                                \
            __half l = __float2half_rn(xs[j] - __half2float(h));              \
            base[OFF_AHI + row * GLDA + a_k4 + j] = h;                        \
            base[OFF_ALO + row * GLDA + a_k4 + j] = l;                        \
        }                                                                     \
    }                                                                         \
    _Pragma("unroll")                                                         \
    for (int p = 0; p < 4; p++) {                                             \
        float xs[4] = {rb[p].x, rb[p].y, rb[p].z, rb[p].w};                   \
        const int kk = b_kk + p * 8;                                          \
        _Pragma("unroll")                                                     \
        for (int j = 0; j < 4; j++) {                                         \
            __half h = __float2half_rn(xs[j]);                                \
            __half l = __float2half_rn(xs[j] - __half2float(h));              \
            base[OFF_BHI + (b_n4 + j) * GLDB + kk] = h;                       \
            base[OFF_BLO + (b_n4 + j) * GLDB + kk] = l;                       \
        }                                                                     \
    }                                                                         \
} while (0)

    LOAD_REGS(0);
    STORE_SMEM(0);

    for (int s = 0; s < nSlab; s++) {
        __syncthreads();
        if (s + 1 < nSlab) LOAD_REGS(s + 1);

        const __half* base = sh + (s & 1) * BUF_HALVES;
#pragma unroll
        for (int ks = 0; ks < 2; ks++) {
            const int k16 = ks * 16;
            uint32_t ah[2][4], al[2][4];
#pragma unroll
            for (int mt = 0; mt < 2; mt++) {
                const int row = warpM * 32 + mt * 16 + gid;
                const int c0  = row * GLDA + k16 + tid2;
                ah[mt][0] = *(const uint32_t*)(base + OFF_AHI + c0);
                ah[mt][1] = *(const uint32_t*)(base + OFF_AHI + c0 + 8 * GLDA);
                ah[mt][2] = *(const uint32_t*)(base + OFF_AHI + c0 + 8);
                ah[mt][3] = *(const uint32_t*)(base + OFF_AHI + c0 + 8 * GLDA + 8);
                al[mt][0] = *(const uint32_t*)(base + OFF_ALO + c0);
                al[mt][1] = *(const uint32_t*)(base + OFF_ALO + c0 + 8 * GLDA);
                al[mt][2] = *(const uint32_t*)(base + OFF_ALO + c0 + 8);
                al[mt][3] = *(const uint32_t*)(base + OFF_ALO + c0 + 8 * GLDA + 8);
            }
#pragma unroll
            for (int nf = 0; nf < 8; nf++) {
                const int nrow = warpN * 64 + nf * 8 + gid;
                const int b0   = nrow * GLDB + k16 + tid2;
                uint32_t bh0 = *(const uint32_t*)(base + OFF_BHI + b0);
                uint32_t bh1 = *(const uint32_t*)(base + OFF_BHI + b0 + 8);
                uint32_t bl0 = *(const uint32_t*)(base + OFF_BLO + b0);
                uint32_t bl1 = *(const uint32_t*)(base + OFF_BLO + b0 + 8);
#pragma unroll
                for (int mt = 0; mt < 2; mt++) {
                    MMA16816(acc[mt][nf], ah[mt], bh0, bh1);
                    MMA16816(acc[mt][nf], al[mt], bh0, bh1);
                    MMA16816(acc[mt][nf], ah[mt], bl0, bl1);
                }
            }
        }

        if (s + 1 < nSlab) STORE_SMEM((s + 1) & 1);
    }

    // ---- epilogue ----
#pragma unroll
    for (int mt = 0; mt < 2; mt++) {
        const int row0 = m0 + warpM * 32 + mt * 16 + gid;
#pragma unroll
        for (int nf = 0; nf < 8; nf++) {
            const int col = z * cZStride + n0 + warpN * 64 + nf * 8 + tid2;
            *(float2*)(C + (long long)row0 * ldc + col) =
                make_float2(acc[mt][nf][0], acc[mt][nf][1]);
            *(float2*)(C + (long long)(row0 + 8) * ldc + col) =
                make_float2(acc[mt][nf][2], acc[mt][nf][3]);
        }
    }
#undef LOAD_REGS
#undef STORE_SMEM
}

// ---------------------------------------------------------------------------
// RoPE (interleaved output layout, matching jnp.stack([r1,r2],-1).reshape)
// ---------------------------------------------------------------------------
__global__ void rope_kernel(float* __restrict__ data, int nheads, float scale)
{
    long long bid = blockIdx.x;
    int t = (int)((bid / nheads) % S_);
    int i = threadIdx.x;
    float* p = data + bid * H_;

    float x1 = p[i];
    float x2 = p[i + 128];

    float ex       = (float)(2 * i) * (1.0f / (float)H_);
    float inv_freq = powf(10000.0f, -ex);
    float ff       = (float)t * inv_freq;
    double fr = (double)ff;
    const double TWO_PI = 6.283185307179586476925286766559;
    fr = fr - floor(fr / TWO_PI) * TWO_PI;
    float c = cosf((float)fr);
    float s = sinf((float)fr);

    __syncthreads();
    p[2 * i]     = (x1 * c - x2 * s) * scale;
    p[2 * i + 1] = (x2 * c + x1 * s) * scale;
}

// ---------------------------------------------------------------------------
// Flash-style sliding-window causal attention with tanh soft-cap (fp32 SIMT)
// ---------------------------------------------------------------------------
#define ATTN_SMEM_FLOATS (3 * 256 * 64 + 64 * 68)
#define ATTN_SMEM_BYTES  (ATTN_SMEM_FLOATS * 4)

__global__ void __launch_bounds__(256, 1) attn_kernel()
{
    extern __shared__ float sm[];
    float* Qs = sm;
    float* Ks = sm + 256 * 64;
    float* Vs = sm + 2 * 256 * 64;
    float* Ps = sm + 3 * 256 * 64;

    const int tid = threadIdx.x;
    const int tx  = tid & 15;
    const int ty  = tid >> 4;
    const int qt0 = blockIdx.x * 64;
    const int bn  = blockIdx.y;
    const int b   = bn / NQ_;
    const int n   = bn % NQ_;
    const int kvh = n >> 1;

    {
        int s = tid & 63;
        int hg0 = tid >> 6;
        const float* qb = g_q + (((long long)(b * S_) + qt0 + s) * NQ_ + n) * H_;
#pragma unroll
        for (int it = 0; it < 16; it++) {
            int hg = hg0 + it * 4;
            float4 v = *(const float4*)(qb + hg * 4);
            Qs[(hg * 4 + 0) * 64 + s] = v.x;
            Qs[(hg * 4 + 1) * 64 + s] = v.y;
            Qs[(hg * 4 + 2) * 64 + s] = v.z;
            Qs[(hg * 4 + 3) * 64 + s] = v.w;
        }
    }

    float o[4][16];
#pragma unroll
    for (int i = 0; i < 4; i++)
#pragma unroll
        for (int c = 0; c < 16; c++) o[i][c] = 0.f;

    float m_i[4], l_i[4];
#pragma unroll
    for (int i = 0; i < 4; i++) { m_i[i] = -1e30f; l_i[i] = 0.f; }

    int lo = qt0 - (WINDOW_ - 1); if (lo < 0) lo = 0;
    const int kt_lo = lo >> 6;
    const int kt_hi = blockIdx.x;

    const float* kbase = g_k + ((long long)(b * S_) * NKV_ + kvh) * H_;
    const float* vbase = g_v + ((long long)(b * S_) * NKV_ + kvh) * H_;

    for (int kt = kt_lo; kt <= kt_hi; kt++) {
        const int kt0 = kt << 6;
        __syncthreads();

        {
            int s = tid & 63;
            int hg0 = tid >> 6;
            const float* kb = kbase + (long long)(kt0 + s) * (NKV_ * H_);
#pragma unroll
            for (int it = 0; it < 16; it++) {
                int hg = hg0 + it * 4;
                float4 v = *(const float4*)(kb + hg * 4);
                Ks[(hg * 4 + 0) * 64 + s] = v.x;
                Ks[(hg * 4 + 1) * 64 + s] = v.y;
                Ks[(hg * 4 + 2) * 64 + s] = v.z;
                Ks[(hg * 4 + 3) * 64 + s] = v.w;
            }
        }
        {
#pragma unroll
            for (int it = 0; it < 16; it++) {
                int idx = it * 256 + tid;
                int s = idx >> 6, hg = idx & 63;
                float4 v = *(const float4*)(vbase + (long long)(kt0 + s) * (NKV_ * H_) + hg * 4);
                *(float4*)&Vs[s * 256 + hg * 4] = v;
            }
        }
        __syncthreads();

        float acc[4][4];
#pragma unroll
        for (int i = 0; i < 4; i++)
#pragma unroll
            for (int j = 0; j < 4; j++) acc[i][j] = 0.f;

#pragma unroll 8
        for (int h = 0; h < 256; h++) {
            float4 q4 = *(const float4*)&Qs[h * 64 + ty * 4];
            float4 k4 = *(const float4*)&Ks[h * 64 + tx * 4];
            float qa[4] = {q4.x, q4.y, q4.z, q4.w};
            float ka[4] = {k4.x, k4.y, k4.z, k4.w};
#pragma unroll
            for (int i = 0; i < 4; i++)
#pragma unroll
                for (int j = 0; j < 4; j++) acc[i][j] = fmaf(qa[i], ka[j], acc[i][j]);
        }

        float rmax[4] = {-1e30f, -1e30f, -1e30f, -1e30f};
#pragma unroll
        for (int i = 0; i < 4; i++) {
            const int tg = qt0 + ty * 4 + i;
#pragma unroll
            for (int j = 0; j < 4; j++) {
                const int sg = kt0 + tx * 4 + j;
                float xv = acc[i][j] * 0.02f;
                xv = fminf(fmaxf(xv, -15.f), 15.f);
                float e  = __expf(2.f * xv);
                float lv = 50.f * (e - 1.f) / (e + 1.f);
                if (sg > tg || sg <= tg - WINDOW_) lv = -1e30f;
                acc[i][j] = lv;
                rmax[i] = fmaxf(rmax[i], lv);
            }
        }
#pragma unroll
        for (int i = 0; i < 4; i++) {
            rmax[i] = fmaxf(rmax[i], __shfl_xor_sync(0xffffffffu, rmax[i], 8, 16));
            rmax[i] = fmaxf(rmax[i], __shfl_xor_sync(0xffffffffu, rmax[i], 4, 16));
            rmax[i] = fmaxf(rmax[i], __shfl_xor_sync(0xffffffffu, rmax[i], 2, 16));
            rmax[i] = fmaxf(rmax[i], __shfl_xor_sync(0xffffffffu, rmax[i], 1, 16));
        }
        float alpha[4], rsum[4] = {0.f, 0.f, 0.f, 0.f};
#pragma unroll
        for (int i = 0; i < 4; i++) {
            float mn = fmaxf(m_i[i], rmax[i]);
            alpha[i] = __expf(m_i[i] - mn);
            m_i[i] = mn;
        }
#pragma unroll
        for (int i = 0; i < 4; i++)
#pragma unroll
            for (int j = 0; j < 4; j++) {
                float p = (acc[i][j] > -1e29f) ? __expf(acc[i][j] - m_i[i]) : 0.f;
                acc[i][j] = p;
                rsum[i] += p;
            }
#pragma unroll
        for (int i = 0; i < 4; i++) {
            rsum[i] += __shfl_xor_sync(0xffffffffu, rsum[i], 8, 16);
            rsum[i] += __shfl_xor_sync(0xffffffffu, rsum[i], 4, 16);
            rsum[i] += __shfl_xor_sync(0xffffffffu, rsum[i], 2, 16);
            rsum[i] += __shfl_xor_sync(0xffffffffu, rsum[i], 1, 16);
            l_i[i] = l_i[i] * alpha[i] + rsum[i];
        }
#pragma unroll
        for (int i = 0; i < 4; i++)
#pragma unroll
            for (int c = 0; c < 16; c++) o[i][c] *= alpha[i];

#pragma unroll
        for (int i = 0; i < 4; i++)
#pragma unroll
            for (int j = 0; j < 4; j++)
                Ps[(tx * 4 + j) * 68 + ty * 4 + i] = acc[i][j];
        __syncthreads();

#pragma unroll 4
        for (int j = 0; j < 64; j++) {
            float4 p4 = *(const float4*)&Ps[j * 68 + ty * 4];
            float pr[4] = {p4.x, p4.y, p4.z, p4.w};
#pragma unroll
            for (int c4 = 0; c4 < 4; c4++) {
                float4 v4 = *(const float4*)&Vs[j * 256 + tx * 16 + c4 * 4];
#pragma unroll
                for (int i = 0; i < 4; i++) {
                    o[i][c4 * 4 + 0] = fmaf(pr[i], v4.x, o[i][c4 * 4 + 0]);
                    o[i][c4 * 4 + 1] = fmaf(pr[i], v4.y, o[i][c4 * 4 + 1]);
                    o[i][c4 * 4 + 2] = fmaf(pr[i], v4.z, o[i][c4 * 4 + 2]);
                    o[i][c4 * 4 + 3] = fmaf(pr[i], v4.w, o[i][c4 * 4 + 3]);
                }
            }
        }
    }

#pragma unroll
    for (int i = 0; i < 4; i++) {
        float inv = 1.0f / l_i[i];
        long long row = ((long long)(b * S_) + qt0 + ty * 4 + i) * NQ_ + n;
        float* op = g_av + row * H_ + tx * 16;
#pragma unroll
        for (int c4 = 0; c4 < 4; c4++) {
            float4 w = make_float4(o[i][c4 * 4 + 0] * inv, o[i][c4 * 4 + 1] * inv,
                                   o[i][c4 * 4 + 2] * inv, o[i][c4 * 4 + 3] * inv);
            *(float4*)(op + c4 * 4) = w;
        }
    }
}

// ---------------------------------------------------------------------------
// Launch
// ---------------------------------------------------------------------------
extern "C" void kernel_launch(void* const* d_in, const int* in_sizes, int n_in,
                              void* d_out, int out_size)
{
    const float* x  = (const float*)d_in[0];
    const float* Wq = (const float*)d_in[1];
    const float* Wk = (const float*)d_in[2];
    const float* Wv = (const float*)d_in[3];
    const float* Wo = (const float*)d_in[4];
    float* out = (float*)d_out;

    float *q, *k, *v, *av;
    cudaGetSymbolAddress((void**)&q,  g_q);
    cudaGetSymbolAddress((void**)&k,  g_k);
    cudaGetSymbolAddress((void**)&v,  g_v);
    cudaGetSymbolAddress((void**)&av, g_av);

    const int M = B_ * S_;      // 4096

    cudaFuncSetAttribute(mma_gemm_kernel, cudaFuncAttributeMaxDynamicSharedMemorySize, GEMM_SMEM_BYTES);
    cudaFuncSetAttribute(attn_kernel, cudaFuncAttributeMaxDynamicSharedMemorySize, ATTN_SMEM_BYTES);

    // QKV projections (per-head GEMM 4096 x 256 x 2048; H=256 -> 2 n-tiles)
    mma_gemm_kernel<<<dim3(H_ / 128, M / 128, NQ_),  256, GEMM_SMEM_BYTES>>>(
        x, D_, Wq, H_, (long long)D_ * H_, q, NQ_ * H_, H_, D_);
    mma_gemm_kernel<<<dim3(H_ / 128, M / 128, NKV_), 256, GEMM_SMEM_BYTES>>>(
        x, D_, Wk, H_, (long long)D_ * H_, k, NKV_ * H_, H_, D_);
    mma_gemm_kernel<<<dim3(H_ / 128, M / 128, NKV_), 256, GEMM_SMEM_BYTES>>>(
        x, D_, Wv, H_, (long long)D_ * H_, v, NKV_ * H_, H_, D_);

    // RoPE (q also scaled by 1/sqrt(H)=1/16)
    rope_kernel<<<M * NQ_,  128>>>(q, NQ_,  0.0625f);
    rope_kernel<<<M * NKV_, 128>>>(k, NKV_, 1.0f);

    // Attention
    attn_kernel<<<dim3(S_ / 64, B_ * NQ_), 256, ATTN_SMEM_BYTES>>>();

    // Output projection: 4096 x 2048 x 4096
    mma_gemm_kernel<<<dim3(D_ / 128, M / 128, 1), 256, GEMM_SMEM_BYTES>>>(
        av, NQ_ * H_, Wo, D_, 0, out, D_, 0, NQ_ * H_);
}

// round 4
// speedup vs baseline: 1.7451x; 1.6613x over previous
#include <cuda_runtime.h>
#include <cuda_fp16.h>
#include <cstdint>
#include <math.h>

#define B_     2
#define S_     2048
#define D_     2048
#define NQ_    16
#define NKV_   8
#define H_     256
#define WINDOW_ 1024

// ---------------------------------------------------------------------------
// Scratch (static device globals; no allocation anywhere)
// ---------------------------------------------------------------------------
__device__ float g_q [B_*S_*NQ_ *H_];   // [b][t][n][h]
__device__ float g_k [B_*S_*NKV_*H_];
__device__ float g_v [B_*S_*NKV_*H_];
__device__ float g_av[B_*S_*NQ_ *H_];

// split-fp16 buffers
__device__ __half g_xh [4096*2048];
__device__ __half g_xl [4096*2048];
__device__ __half g_wqh[16*256*2048];   // [z][N=256][K=2048]
__device__ __half g_wql[16*256*2048];
__device__ __half g_wkh[8*256*2048];
__device__ __half g_wkl[8*256*2048];
__device__ __half g_wvh[8*256*2048];
__device__ __half g_wvl[8*256*2048];
__device__ __half g_woh[2048*4096];     // [N=2048][K=4096]
__device__ __half g_wol[2048*4096];
__device__ __half g_avh[4096*4096];
__device__ __half g_avl[4096*4096];

// ---------------------------------------------------------------------------
// Elementwise fp32 -> (hi, lo) fp16 split
// ---------------------------------------------------------------------------
__global__ void __launch_bounds__(256) convert_split_kernel(
    const float* __restrict__ src, __half* __restrict__ hi, __half* __restrict__ lo, int n4)
{
    int idx = blockIdx.x * 256 + threadIdx.x;
    if (idx >= n4) return;
    float4 v = ((const float4*)src)[idx];
    __half h0 = __float2half_rn(v.x), h1 = __float2half_rn(v.y);
    __half h2 = __float2half_rn(v.z), h3 = __float2half_rn(v.w);
    __half l0 = __float2half_rn(v.x - __half2float(h0));
    __half l1 = __float2half_rn(v.y - __half2float(h1));
    __half l2 = __float2half_rn(v.z - __half2float(h2));
    __half l3 = __float2half_rn(v.w - __half2float(h3));
    ((__half2*)hi)[idx * 2]     = __halves2half2(h0, h1);
    ((__half2*)hi)[idx * 2 + 1] = __halves2half2(h2, h3);
    ((__half2*)lo)[idx * 2]     = __halves2half2(l0, l1);
    ((__half2*)lo)[idx * 2 + 1] = __halves2half2(l2, l3);
}

// ---------------------------------------------------------------------------
// Weight transpose + split: src [z][K][N] fp32 -> dst [z][N][K] (hi, lo) fp16
// ---------------------------------------------------------------------------
__global__ void __launch_bounds__(256) convert_wt_kernel(
    const float* __restrict__ src, __half* __restrict__ hi, __half* __restrict__ lo,
    int K, int N)
{
    __shared__ float t[32][33];
    const int z = blockIdx.z;
    const float* s = src + (long long)z * K * N;
    __half* hz = hi + (long long)z * K * N;
    __half* lz = lo + (long long)z * K * N;
    const int n0 = blockIdx.x * 32, k0 = blockIdx.y * 32;
    const int x = threadIdx.x, y = threadIdx.y;
#pragma unroll
    for (int i = 0; i < 4; i++)
        t[y + 8 * i][x] = s[(long long)(k0 + y + 8 * i) * N + n0 + x];
    __syncthreads();
#pragma unroll
    for (int i = 0; i < 4; i++) {
        float v = t[x][y + 8 * i];
        __half h = __float2half_rn(v);
        __half l = __float2half_rn(v - __half2float(h));
        hz[(long long)(n0 + y + 8 * i) * K + k0 + x] = h;
        lz[(long long)(n0 + y + 8 * i) * K + k0 + x] = l;
    }
}

// ===========================================================================
// fp16x3 mma.sync GEMM with cp.async + ldmatrix + SW128 swizzle.
// C[M,N] fp32 = A[M,K] * B^T  where A=(Ah+Al) [M][K], B=(Bh+Bl) [z][N][K].
// Tile 128x128x64, 256 thr = 8 warps (4M x 2N), warp tile 32x64. 2 stages.
// ===========================================================================
#define AHI_B 0
#define ALO_B 16384
#define BHI_B 32768
#define BLO_B 49152
#define STAGE_B 65536
#define HGEMM_SMEM (2 * STAGE_B)   // 131072 bytes

__device__ __forceinline__ uint32_t smem_u32(const void* p) {
    uint32_t a;
    asm("{ .reg .u64 t; cvta.to.shared.u64 t, %1; cvt.u32.u64 %0, t; }" : "=r"(a) : "l"(p));
    return a;
}

#define MMA16816(c, a, b0, b1)                                               \
    asm volatile("mma.sync.aligned.m16n8k16.row.col.f32.f16.f16.f32 "        \
        "{%0,%1,%2,%3}, {%4,%5,%6,%7}, {%8,%9}, {%0,%1,%2,%3};"              \
        : "+f"((c)[0]), "+f"((c)[1]), "+f"((c)[2]), "+f"((c)[3])             \
        : "r"((a)[0]), "r"((a)[1]), "r"((a)[2]), "r"((a)[3]),                \
          "r"(b0), "r"(b1))

#define LDMX4(d, addr)                                                       \
    asm volatile("ldmatrix.sync.aligned.m8n8.x4.shared.b16 {%0,%1,%2,%3}, [%4];" \
        : "=r"((d)[0]), "=r"((d)[1]), "=r"((d)[2]), "=r"((d)[3]) : "r"(addr))

#define CP16(dst, src)                                                       \
    asm volatile("cp.async.cg.shared.global [%0], [%1], 16;" :: "r"(dst), "l"(src))

#define SWZ(byte) ((byte) ^ (((byte) >> 3) & 0x70))

__global__ void __launch_bounds__(256, 1)
hgemm3_kernel(const __half* __restrict__ Ah, const __half* __restrict__ Al, int K,
              const __half* __restrict__ Bh, const __half* __restrict__ Bl,
              long long bZStride, float* __restrict__ C, int ldc, int cZStride)
{
    extern __shared__ __half hsm[];
    const uint32_t sb = smem_u32(hsm);

    const int tid  = threadIdx.x;
    const int wid  = tid >> 5;
    const int lane = tid & 31;
    const int gid  = lane >> 2;
    const int tid2 = (lane & 3) * 2;
    const int warpM = wid & 3;
    const int warpN = wid >> 2;
    const int lrow = lane & 15;
    const int lsel = lane >> 4;

    const int m0 = blockIdx.y * 128;
    const int n0 = blockIdx.x * 128;
    const int z  = blockIdx.z;
    const __half* Bhp = Bh + (long long)z * bZStride;
    const __half* Blp = Bl + (long long)z * bZStride;

    float acc[2][8][4];
#pragma unroll
    for (int mt = 0; mt < 2; mt++)
#pragma unroll
        for (int nf = 0; nf < 8; nf++)
#pragma unroll
            for (int r = 0; r < 4; r++) acc[mt][nf][r] = 0.f;

    const int nSlab = K >> 6;

#define FILL(stage, s) do {                                                   \
    const int k0f = (s) << 6;                                                 \
    const uint32_t stBase = sb + (uint32_t)(stage) * STAGE_B;                 \
    _Pragma("unroll")                                                         \
    for (int p = 0; p < 4; p++) {                                             \
        const int chunk = p * 256 + tid;                                      \
        const int row = chunk >> 3;                                           \
        const int c16 = chunk & 7;                                            \
        const uint32_t byte = (uint32_t)(row * 128 + c16 * 16);               \
        const uint32_t swz = SWZ(byte);                                       \
        const long long ka = (long long)(m0 + row) * K + k0f + c16 * 8;       \
        const long long kb = (long long)(n0 + row) * K + k0f + c16 * 8;       \
        CP16(stBase + AHI_B + swz, Ah + ka);                                  \
        CP16(stBase + ALO_B + swz, Al + ka);                                  \
        CP16(stBase + BHI_B + swz, Bhp + kb);                                 \
        CP16(stBase + BLO_B + swz, Blp + kb);                                 \
    }                                                                         \
    asm volatile("cp.async.commit_group;" ::: "memory");                      \
} while (0)

    FILL(0, 0);

    for (int s = 0; s < nSlab; s++) {
        asm volatile("cp.async.wait_group 0;" ::: "memory");
        __syncthreads();
        if (s + 1 < nSlab) FILL((s + 1) & 1, s + 1);

        const uint32_t stBase = sb + (uint32_t)(s & 1) * STAGE_B;
#pragma unroll
        for (int ks = 0; ks < 4; ks++) {
            const int ck = ks * 2 + lsel;
            uint32_t ah[2][4], al[2][4], bh[4][4], bl[4][4];
#pragma unroll
            for (int mt = 0; mt < 2; mt++) {
                const int row = warpM * 32 + mt * 16 + lrow;
                const uint32_t swz = SWZ((uint32_t)(row * 128 + ck * 16));
                LDMX4(ah[mt], stBase + AHI_B + swz);
                LDMX4(al[mt], stBase + ALO_B + swz);
            }
#pragma unroll
            for (int ng = 0; ng < 4; ng++) {
                const int row = warpN * 64 + ng * 16 + lrow;
                const uint32_t swz = SWZ((uint32_t)(row * 128 + ck * 16));
                LDMX4(bh[ng], stBase + BHI_B + swz);
                LDMX4(bl[ng], stBase + BLO_B + swz);
            }
#pragma unroll
            for (int ng = 0; ng < 4; ng++)
#pragma unroll
                for (int h = 0; h < 2; h++) {
                    const int nf = ng * 2 + h;
                    const uint32_t b0h = bh[ng][h], b1h = bh[ng][2 + h];
                    const uint32_t b0l = bl[ng][h], b1l = bl[ng][2 + h];
#pragma unroll
                    for (int mt = 0; mt < 2; mt++) {
                        MMA16816(acc[mt][nf], ah[mt], b0h, b1h);
                        MMA16816(acc[mt][nf], al[mt], b0h, b1h);
                        MMA16816(acc[mt][nf], ah[mt], b0l, b1l);
                    }
                }
        }
    }
#undef FILL

    // ---- epilogue ----
#pragma unroll
    for (int mt = 0; mt < 2; mt++) {
        const int row0 = m0 + warpM * 32 + mt * 16 + gid;
#pragma unroll
        for (int nf = 0; nf < 8; nf++) {
            const int col = z * cZStride + n0 + warpN * 64 + nf * 8 + tid2;
            *(float2*)(C + (long long)row0 * ldc + col) =
                make_float2(acc[mt][nf][0], acc[mt][nf][1]);
            *(float2*)(C + (long long)(row0 + 8) * ldc + col) =
                make_float2(acc[mt][nf][2], acc[mt][nf][3]);
        }
    }
}

// ---------------------------------------------------------------------------
// RoPE (interleaved output layout, matching jnp.stack([r1,r2],-1).reshape)
// ---------------------------------------------------------------------------
__global__ void rope_kernel(float* __restrict__ data, int nheads, float scale)
{
    long long bid = blockIdx.x;
    int t = (int)((bid / nheads) % S_);
    int i = threadIdx.x;
    float* p = data + bid * H_;

    float x1 = p[i];
    float x2 = p[i + 128];

    float ex       = (float)(2 * i) * (1.0f / (float)H_);
    float inv_freq = powf(10000.0f, -ex);
    float ff       = (float)t * inv_freq;
    double fr = (double)ff;
    const double TWO_PI = 6.283185307179586476925286766559;
    fr = fr - floor(fr / TWO_PI) * TWO_PI;
    float c = cosf((float)fr);
    float s = sinf((float)fr);

    __syncthreads();
    p[2 * i]     = (x1 * c - x2 * s) * scale;
    p[2 * i + 1] = (x2 * c + x1 * s) * scale;
}

// ---------------------------------------------------------------------------
// Flash-style sliding-window causal attention with tanh soft-cap (fp32 SIMT)
// ---------------------------------------------------------------------------
#define ATTN_SMEM_FLOATS (3 * 256 * 64 + 64 * 68)
#define ATTN_SMEM_BYTES  (ATTN_SMEM_FLOATS * 4)

__global__ void __launch_bounds__(256, 1) attn_kernel()
{
    extern __shared__ float sm[];
    float* Qs = sm;
    float* Ks = sm + 256 * 64;
    float* Vs = sm + 2 * 256 * 64;
    float* Ps = sm + 3 * 256 * 64;

    const int tid = threadIdx.x;
    const int tx  = tid & 15;
    const int ty  = tid >> 4;
    const int qt0 = blockIdx.x * 64;
    const int bn  = blockIdx.y;
    const int b   = bn / NQ_;
    const int n   = bn % NQ_;
    const int kvh = n >> 1;

    {
        int s = tid & 63;
        int hg0 = tid >> 6;
        const float* qb = g_q + (((long long)(b * S_) + qt0 + s) * NQ_ + n) * H_;
#pragma unroll
        for (int it = 0; it < 16; it++) {
            int hg = hg0 + it * 4;
            float4 v = *(const float4*)(qb + hg * 4);
            Qs[(hg * 4 + 0) * 64 + s] = v.x;
            Qs[(hg * 4 + 1) * 64 + s] = v.y;
            Qs[(hg * 4 + 2) * 64 + s] = v.z;
            Qs[(hg * 4 + 3) * 64 + s] = v.w;
        }
    }

    float o[4][16];
#pragma unroll
    for (int i = 0; i < 4; i++)
#pragma unroll
        for (int c = 0; c < 16; c++) o[i][c] = 0.f;

    float m_i[4], l_i[4];
#pragma unroll
    for (int i = 0; i < 4; i++) { m_i[i] = -1e30f; l_i[i] = 0.f; }

    int lo = qt0 - (WINDOW_ - 1); if (lo < 0) lo = 0;
    const int kt_lo = lo >> 6;
    const int kt_hi = blockIdx.x;

    const float* kbase = g_k + ((long long)(b * S_) * NKV_ + kvh) * H_;
    const float* vbase = g_v + ((long long)(b * S_) * NKV_ + kvh) * H_;

    for (int kt = kt_lo; kt <= kt_hi; kt++) {
        const int kt0 = kt << 6;
        __syncthreads();

        {
            int s = tid & 63;
            int hg0 = tid >> 6;
            const float* kb = kbase + (long long)(kt0 + s) * (NKV_ * H_);
#pragma unroll
            for (int it = 0; it < 16; it++) {
                int hg = hg0 + it * 4;
                float4 v = *(const float4*)(kb + hg * 4);
                Ks[(hg * 4 + 0) * 64 + s] = v.x;
                Ks[(hg * 4 + 1) * 64 + s] = v.y;
                Ks[(hg * 4 + 2) * 64 + s] = v.z;
                Ks[(hg * 4 + 3) * 64 + s] = v.w;
            }
        }
        {
#pragma unroll
            for (int it = 0; it < 16; it++) {
                int idx = it * 256 + tid;
                int s = idx >> 6, hg = idx & 63;
                float4 v = *(const float4*)(vbase + (long long)(kt0 + s) * (NKV_ * H_) + hg * 4);
                *(float4*)&Vs[s * 256 + hg * 4] = v;
            }
        }
        __syncthreads();

        float acc[4][4];
#pragma unroll
        for (int i = 0; i < 4; i++)
#pragma unroll
            for (int j = 0; j < 4; j++) acc[i][j] = 0.f;

#pragma unroll 8
        for (int h = 0; h < 256; h++) {
            float4 q4 = *(const float4*)&Qs[h * 64 + ty * 4];
            float4 k4 = *(const float4*)&Ks[h * 64 + tx * 4];
            float qa[4] = {q4.x, q4.y, q4.z, q4.w};
            float ka[4] = {k4.x, k4.y, k4.z, k4.w};
#pragma unroll
            for (int i = 0; i < 4; i++)
#pragma unroll
                for (int j = 0; j < 4; j++) acc[i][j] = fmaf(qa[i], ka[j], acc[i][j]);
        }

        float rmax[4] = {-1e30f, -1e30f, -1e30f, -1e30f};
#pragma unroll
        for (int i = 0; i < 4; i++) {
            const int tg = qt0 + ty * 4 + i;
#pragma unroll
            for (int j = 0; j < 4; j++) {
                const int sg = kt0 + tx * 4 + j;
                float xv = acc[i][j] * 0.02f;
                xv = fminf(fmaxf(xv, -15.f), 15.f);
                float e  = __expf(2.f * xv);
                float lv = 50.f * (e - 1.f) / (e + 1.f);
                if (sg > tg || sg <= tg - WINDOW_) lv = -1e30f;
                acc[i][j] = lv;
                rmax[i] = fmaxf(rmax[i], lv);
            }
        }
#pragma unroll
        for (int i = 0; i < 4; i++) {
            rmax[i] = fmaxf(rmax[i], __shfl_xor_sync(0xffffffffu, rmax[i], 8, 16));
            rmax[i] = fmaxf(rmax[i], __shfl_xor_sync(0xffffffffu, rmax[i], 4, 16));
            rmax[i] = fmaxf(rmax[i], __shfl_xor_sync(0xffffffffu, rmax[i], 2, 16));
            rmax[i] = fmaxf(rmax[i], __shfl_xor_sync(0xffffffffu, rmax[i], 1, 16));
        }
        float alpha[4], rsum[4] = {0.f, 0.f, 0.f, 0.f};
#pragma unroll
        for (int i = 0; i < 4; i++) {
            float mn = fmaxf(m_i[i], rmax[i]);
            alpha[i] = __expf(m_i[i] - mn);
            m_i[i] = mn;
        }
#pragma unroll
        for (int i = 0; i < 4; i++)
#pragma unroll
            for (int j = 0; j < 4; j++) {
                float p = (acc[i][j] > -1e29f) ? __expf(acc[i][j] - m_i[i]) : 0.f;
                acc[i][j] = p;
                rsum[i] += p;
            }
#pragma unroll
        for (int i = 0; i < 4; i++) {
            rsum[i] += __shfl_xor_sync(0xffffffffu, rsum[i], 8, 16);
            rsum[i] += __shfl_xor_sync(0xffffffffu, rsum[i], 4, 16);
            rsum[i] += __shfl_xor_sync(0xffffffffu, rsum[i], 2, 16);
            rsum[i] += __shfl_xor_sync(0xffffffffu, rsum[i], 1, 16);
            l_i[i] = l_i[i] * alpha[i] + rsum[i];
        }
#pragma unroll
        for (int i = 0; i < 4; i++)
#pragma unroll
            for (int c = 0; c < 16; c++) o[i][c] *= alpha[i];

#pragma unroll
        for (int i = 0; i < 4; i++)
#pragma unroll
            for (int j = 0; j < 4; j++)
                Ps[(tx * 4 + j) * 68 + ty * 4 + i] = acc[i][j];
        __syncthreads();

#pragma unroll 4
        for (int j = 0; j < 64; j++) {
            float4 p4 = *(const float4*)&Ps[j * 68 + ty * 4];
            float pr[4] = {p4.x, p4.y, p4.z, p4.w};
#pragma unroll
            for (int c4 = 0; c4 < 4; c4++) {
                float4 v4 = *(const float4*)&Vs[j * 256 + tx * 16 + c4 * 4];
#pragma unroll
                for (int i = 0; i < 4; i++) {
                    o[i][c4 * 4 + 0] = fmaf(pr[i], v4.x, o[i][c4 * 4 + 0]);
                    o[i][c4 * 4 + 1] = fmaf(pr[i], v4.y, o[i][c4 * 4 + 1]);
                    o[i][c4 * 4 + 2] = fmaf(pr[i], v4.z, o[i][c4 * 4 + 2]);
                    o[i][c4 * 4 + 3] = fmaf(pr[i], v4.w, o[i][c4 * 4 + 3]);
                }
            }
        }
    }

#pragma unroll
    for (int i = 0; i < 4; i++) {
        float inv = 1.0f / l_i[i];
        long long row = ((long long)(b * S_) + qt0 + ty * 4 + i) * NQ_ + n;
        float* op = g_av + row * H_ + tx * 16;
#pragma unroll
        for (int c4 = 0; c4 < 4; c4++) {
            float4 w = make_float4(o[i][c4 * 4 + 0] * inv, o[i][c4 * 4 + 1] * inv,
                                   o[i][c4 * 4 + 2] * inv, o[i][c4 * 4 + 3] * inv);
            *(float4*)(op + c4 * 4) = w;
        }
    }
}

// ---------------------------------------------------------------------------
// Launch
// ---------------------------------------------------------------------------
extern "C" void kernel_launch(void* const* d_in, const int* in_sizes, int n_in,
                              void* d_out, int out_size)
{
    const float* x  = (const float*)d_in[0];
    const float* Wq = (const float*)d_in[1];
    const float* Wk = (const float*)d_in[2];
    const float* Wv = (const float*)d_in[3];
    const float* Wo = (const float*)d_in[4];
    float* out = (float*)d_out;

    float *q, *k, *v, *av;
    cudaGetSymbolAddress((void**)&q,  g_q);
    cudaGetSymbolAddress((void**)&k,  g_k);
    cudaGetSymbolAddress((void**)&v,  g_v);
    cudaGetSymbolAddress((void**)&av, g_av);

    __half *xh, *xl, *wqh, *wql, *wkh, *wkl, *wvh, *wvl, *woh, *wol, *avh, *avl;
    cudaGetSymbolAddress((void**)&xh,  g_xh);  cudaGetSymbolAddress((void**)&xl,  g_xl);
    cudaGetSymbolAddress((void**)&wqh, g_wqh); cudaGetSymbolAddress((void**)&wql, g_wql);
    cudaGetSymbolAddress((void**)&wkh, g_wkh); cudaGetSymbolAddress((void**)&wkl, g_wkl);
    cudaGetSymbolAddress((void**)&wvh, g_wvh); cudaGetSymbolAddress((void**)&wvl, g_wvl);
    cudaGetSymbolAddress((void**)&woh, g_woh); cudaGetSymbolAddress((void**)&wol, g_wol);
    cudaGetSymbolAddress((void**)&avh, g_avh); cudaGetSymbolAddress((void**)&avl, g_avl);

    const int M = B_ * S_;      // 4096

    cudaFuncSetAttribute(hgemm3_kernel, cudaFuncAttributeMaxDynamicSharedMemorySize, HGEMM_SMEM);
    cudaFuncSetAttribute(attn_kernel, cudaFuncAttributeMaxDynamicSharedMemorySize, ATTN_SMEM_BYTES);

    // ---- conversions ----
    {
        int n4 = M * D_ / 4;
        convert_split_kernel<<<(n4 + 255) / 256, 256>>>(x, xh, xl, n4);
    }
    convert_wt_kernel<<<dim3(H_ / 32, D_ / 32, NQ_),  dim3(32, 8)>>>(Wq, wqh, wql, D_, H_);
    convert_wt_kernel<<<dim3(H_ / 32, D_ / 32, NKV_), dim3(32, 8)>>>(Wk, wkh, wkl, D_, H_);
    convert_wt_kernel<<<dim3(H_ / 32, D_ / 32, NKV_), dim3(32, 8)>>>(Wv, wvh, wvl, D_, H_);
    convert_wt_kernel<<<dim3(D_ / 32, (NQ_ * H_) / 32, 1), dim3(32, 8)>>>(Wo, woh, wol, NQ_ * H_, D_);

    // ---- QKV projections ----
    hgemm3_kernel<<<dim3(H_ / 128, M / 128, NQ_),  256, HGEMM_SMEM>>>(
        xh, xl, D_, wqh, wql, (long long)H_ * D_, q, NQ_ * H_, H_);
    hgemm3_kernel<<<dim3(H_ / 128, M / 128, NKV_), 256, HGEMM_SMEM>>>(
        xh, xl, D_, wkh, wkl, (long long)H_ * D_, k, NKV_ * H_, H_);
    hgemm3_kernel<<<dim3(H_ / 128, M / 128, NKV_), 256, HGEMM_SMEM>>>(
        xh, xl, D_, wvh, wvl, (long long)H_ * D_, v, NKV_ * H_, H_);

    // ---- RoPE ----
    rope_kernel<<<M * NQ_,  128>>>(q, NQ_,  0.0625f);
    rope_kernel<<<M * NKV_, 128>>>(k, NKV_, 1.0f);

    // ---- attention ----
    attn_kernel<<<dim3(S_ / 64, B_ * NQ_), 256, ATTN_SMEM_BYTES>>>();

    // ---- output projection ----
    {
        int n4 = M * (NQ_ * H_) / 4;
        convert_split_kernel<<<(n4 + 255) / 256, 256>>>(av, avh, avl, n4);
    }
    hgemm3_kernel<<<dim3(D_ / 128, M / 128, 1), 256, HGEMM_SMEM>>>(
        avh, avl, NQ_ * H_, woh, wol, 0, out, D_, 0);
}

// round 8
// speedup vs baseline: 3.4393x; 1.9708x over previous
#include <cuda_runtime.h>
#include <cuda_fp16.h>
#include <cstdint>
#include <math.h>

#define B_     2
#define S_     2048
#define D_     2048
#define NQ_    16
#define NKV_   8
#define H_     256
#define WINDOW_ 1024

// ---------------- scratch (device globals; no allocation) ----------------
__device__ float g_q [B_*S_*NQ_ *H_];
__device__ float g_k [B_*S_*NKV_*H_];
__device__ float g_v [B_*S_*NKV_*H_];

__device__ __half g_xh [4096*2048];
__device__ __half g_xl [4096*2048];
__device__ __half g_wqh[16*256*2048];
__device__ __half g_wql[16*256*2048];
__device__ __half g_wkh[8*256*2048];
__device__ __half g_wkl[8*256*2048];
__device__ __half g_wvh[8*256*2048];
__device__ __half g_wvl[8*256*2048];
__device__ __half g_woh[2048*4096];
__device__ __half g_wol[2048*4096];
__device__ __half g_avh[4096*4096];
__device__ __half g_avl[4096*4096];
__device__ __half g_qh [B_*S_*NQ_ *H_];
__device__ __half g_ql [B_*S_*NQ_ *H_];
__device__ __half g_kh [B_*S_*NKV_*H_];
__device__ __half g_kl [B_*S_*NKV_*H_];
__device__ __half g_vth[B_*NKV_*H_*S_];   // [b][kvh][h][t]
__device__ __half g_vtl[B_*NKV_*H_*S_];

// ---------------- helpers ----------------
__device__ __forceinline__ uint32_t smem_u32(const void* p) {
    uint32_t a;
    asm("{ .reg .u64 t; cvta.to.shared.u64 t, %1; cvt.u32.u64 %0, t; }" : "=r"(a) : "l"(p));
    return a;
}
#define MMA16816(c, a, b0, b1)                                               \
    asm volatile("mma.sync.aligned.m16n8k16.row.col.f32.f16.f16.f32 "        \
        "{%0,%1,%2,%3}, {%4,%5,%6,%7}, {%8,%9}, {%0,%1,%2,%3};"              \
        : "+f"((c)[0]), "+f"((c)[1]), "+f"((c)[2]), "+f"((c)[3])             \
        : "r"((a)[0]), "r"((a)[1]), "r"((a)[2]), "r"((a)[3]), "r"(b0), "r"(b1))
#define LDMX4(d, addr)                                                       \
    asm volatile("ldmatrix.sync.aligned.m8n8.x4.shared.b16 {%0,%1,%2,%3}, [%4];" \
        : "=r"((d)[0]), "=r"((d)[1]), "=r"((d)[2]), "=r"((d)[3]) : "r"(addr))
#define CP16(dst, src)                                                       \
    asm volatile("cp.async.cg.shared.global [%0], [%1], 16;" :: "r"(dst), "l"(src))
#define CPCOMMIT() asm volatile("cp.async.commit_group;" ::: "memory")
#define CPWAIT0()  asm volatile("cp.async.wait_group 0;" ::: "memory")
#define CPWAIT1()  asm volatile("cp.async.wait_group 1;" ::: "memory")
#define SWZ(byte) ((byte) ^ (((byte) >> 3) & 0x70))

// ---------------- fp32 -> (hi, lo) fp16 elementwise ----------------
__global__ void __launch_bounds__(256) convert_split_kernel(
    const float* __restrict__ src, __half* __restrict__ hi, __half* __restrict__ lo, int n4)
{
    int idx = blockIdx.x * 256 + threadIdx.x;
    if (idx >= n4) return;
    float4 v = ((const float4*)src)[idx];
    __half h0 = __float2half_rn(v.x), h1 = __float2half_rn(v.y);
    __half h2 = __float2half_rn(v.z), h3 = __float2half_rn(v.w);
    ((__half2*)hi)[idx*2]   = __halves2half2(h0, h1);
    ((__half2*)hi)[idx*2+1] = __halves2half2(h2, h3);
    ((__half2*)lo)[idx*2]   = __halves2half2(__float2half_rn(v.x - __half2float(h0)),
                                             __float2half_rn(v.y - __half2float(h1)));
    ((__half2*)lo)[idx*2+1] = __halves2half2(__float2half_rn(v.z - __half2float(h2)),
                                             __float2half_rn(v.w - __half2float(h3)));
}

// ---------------- weight transpose+split [z][K][N] -> [z][N][K] ----------------
__global__ void __launch_bounds__(256) convert_wt_kernel(
    const float* __restrict__ src, __half* __restrict__ hi, __half* __restrict__ lo,
    int K, int N)
{
    __shared__ float t[32][33];
    const int z = blockIdx.z;
    const float* s = src + (long long)z * K * N;
    __half* hz = hi + (long long)z * K * N;
    __half* lz = lo + (long long)z * K * N;
    const int n0 = blockIdx.x * 32, k0 = blockIdx.y * 32;
    const int x = threadIdx.x, y = threadIdx.y;
#pragma unroll
    for (int i = 0; i < 4; i++)
        t[y + 8*i][x] = s[(long long)(k0 + y + 8*i) * N + n0 + x];
    __syncthreads();
#pragma unroll
    for (int i = 0; i < 4; i++) {
        float v = t[x][y + 8*i];
        __half h = __float2half_rn(v);
        hz[(long long)(n0 + y + 8*i) * K + k0 + x] = h;
        lz[(long long)(n0 + y + 8*i) * K + k0 + x] = __float2half_rn(v - __half2float(h));
    }
}

// ---------------- V transpose+split ----------------
__global__ void __launch_bounds__(256) vtrans_kernel()
{
    __shared__ float t[32][33];
    const int z = blockIdx.z;            // b*NKV + kvh
    const int b = z / NKV_, kvh = z % NKV_;
    const int t0 = blockIdx.x * 32, h0 = blockIdx.y * 32;
    const int x = threadIdx.x, y = threadIdx.y;
#pragma unroll
    for (int i = 0; i < 4; i++)
        t[x][y + 8*i] = g_v[(((long long)(b*S_ + t0 + x)) * NKV_ + kvh) * H_ + h0 + y + 8*i];
    __syncthreads();
    const long long obase = ((long long)z * H_) * S_;
#pragma unroll
    for (int i = 0; i < 4; i++) {
        float v = t[x][y + 8*i];
        __half h = __float2half_rn(v);
        long long o = obase + (long long)(h0 + y + 8*i) * S_ + t0 + x;
        g_vth[o] = h;
        g_vtl[o] = __float2half_rn(v - __half2float(h));
    }
}

// ---------------- RoPE + split (scale folded) ----------------
__global__ void rope_split_kernel(const float* __restrict__ src,
                                  __half* __restrict__ hi, __half* __restrict__ lo,
                                  int nheads, float scale)
{
    long long bid = blockIdx.x;
    int t = (int)((bid / nheads) % S_);
    int i = threadIdx.x;
    const float* p = src + bid * H_;
    float x1 = p[i], x2 = p[i + 128];
    float ex = (float)(2*i) * (1.0f / (float)H_);
    float inv_freq = powf(10000.0f, -ex);
    float ff = (float)t * inv_freq;
    double fr = (double)ff;
    const double TWO_PI = 6.283185307179586476925286766559;
    fr = fr - floor(fr / TWO_PI) * TWO_PI;
    float c = cosf((float)fr), s = sinf((float)fr);
    float r1 = (x1 * c - x2 * s) * scale;
    float r2 = (x2 * c + x1 * s) * scale;
    __half h1 = __float2half_rn(r1), h2 = __float2half_rn(r2);
    hi[bid*H_ + 2*i]   = h1;
    hi[bid*H_ + 2*i+1] = h2;
    lo[bid*H_ + 2*i]   = __float2half_rn(r1 - __half2float(h1));
    lo[bid*H_ + 2*i+1] = __float2half_rn(r2 - __half2float(h2));
}

// ================= split-fp16 GEMM (TERMS = 2 or 3) =================
template<int TERMS>
__global__ void __launch_bounds__(256, 1)
hgemm_kernel(const __half* __restrict__ Ah, const __half* __restrict__ Al, int K,
             const __half* __restrict__ Bh, const __half* __restrict__ Bl,
             long long bZStride, float* __restrict__ C, int ldc, int cZStride)
{
    constexpr uint32_t AHI = 0, ALO = 16384, BHI = 32768, BLO = 49152;
    constexpr uint32_t STAGE = (TERMS == 3) ? 65536u : 49152u;
    extern __shared__ __half hsm[];
    const uint32_t sb = smem_u32(hsm);

    const int tid = threadIdx.x, wid = tid >> 5, lane = tid & 31;
    const int gid = lane >> 2, tid2 = (lane & 3) * 2;
    const int warpM = wid & 3, warpN = wid >> 2;
    const int lrow = lane & 15, lsel = lane >> 4;

    const int m0 = blockIdx.y * 128, n0 = blockIdx.x * 128, z = blockIdx.z;
    const __half* Bhp = Bh + (long long)z * bZStride;
    const __half* Blp = Bl + (long long)z * bZStride;

    float acc[2][8][4];
#pragma unroll
    for (int mt = 0; mt < 2; mt++)
#pragma unroll
        for (int nf = 0; nf < 8; nf++)
#pragma unroll
            for (int r = 0; r < 4; r++) acc[mt][nf][r] = 0.f;

    const int nSlab = K >> 6;

#define FILLG(stage, s) do {                                                  \
    const int k0f = (s) << 6;                                                 \
    const uint32_t stBase = sb + (uint32_t)(stage) * STAGE;                   \
    _Pragma("unroll")                                                         \
    for (int p = 0; p < 4; p++) {                                             \
        const int chunk = p * 256 + tid;                                      \
        const int row = chunk >> 3, c16 = chunk & 7;                          \
        const uint32_t swz = SWZ((uint32_t)(row * 128 + c16 * 16));           \
        const long long ka = (long long)(m0 + row) * K + k0f + c16 * 8;       \
        const long long kb = (long long)(n0 + row) * K + k0f + c16 * 8;       \
        CP16(stBase + AHI + swz, Ah + ka);                                    \
        CP16(stBase + ALO + swz, Al + ka);                                    \
        CP16(stBase + BHI + swz, Bhp + kb);                                   \
        if (TERMS == 3) CP16(stBase + BLO + swz, Blp + kb);                   \
    }                                                                         \
    CPCOMMIT();                                                               \
} while (0)

    FILLG(0, 0);
    for (int s = 0; s < nSlab; s++) {
        CPWAIT0();
        __syncthreads();
        if (s + 1 < nSlab) FILLG((s + 1) & 1, s + 1);

        const uint32_t stBase = sb + (uint32_t)(s & 1) * STAGE;
#pragma unroll
        for (int ks = 0; ks < 4; ks++) {
            const int ck = ks * 2 + lsel;
            uint32_t ah[2][4], al[2][4], bh[4][4], bl[4][4];
#pragma unroll
            for (int mt = 0; mt < 2; mt++) {
                const int row = warpM * 32 + mt * 16 + lrow;
                const uint32_t swz = SWZ((uint32_t)(row * 128 + ck * 16));
                LDMX4(ah[mt], stBase + AHI + swz);
                LDMX4(al[mt], stBase + ALO + swz);
            }
#pragma unroll
            for (int ng = 0; ng < 4; ng++) {
                const int row = warpN * 64 + ng * 16 + lrow;
                const uint32_t swz = SWZ((uint32_t)(row * 128 + ck * 16));
                LDMX4(bh[ng], stBase + BHI + swz);
                if (TERMS == 3) LDMX4(bl[ng], stBase + BLO + swz);
            }
#pragma unroll
            for (int ng = 0; ng < 4; ng++)
#pragma unroll
                for (int h = 0; h < 2; h++) {
                    const int nf = ng * 2 + h;
#pragma unroll
                    for (int mt = 0; mt < 2; mt++) {
                        MMA16816(acc[mt][nf], ah[mt], bh[ng][h], bh[ng][2 + h]);
                        MMA16816(acc[mt][nf], al[mt], bh[ng][h], bh[ng][2 + h]);
                        if (TERMS == 3)
                            MMA16816(acc[mt][nf], ah[mt], bl[ng][h], bl[ng][2 + h]);
                    }
                }
        }
    }
#undef FILLG

#pragma unroll
    for (int mt = 0; mt < 2; mt++) {
        const int row0 = m0 + warpM * 32 + mt * 16 + gid;
#pragma unroll
        for (int nf = 0; nf < 8; nf++) {
            const int col = z * cZStride + n0 + warpN * 64 + nf * 8 + tid2;
            *(float2*)(C + (long long)row0 * ldc + col) =
                make_float2(acc[mt][nf][0], acc[mt][nf][1]);
            *(float2*)(C + (long long)(row0 + 8) * ldc + col) =
                make_float2(acc[mt][nf][2], acc[mt][nf][3]);
        }
    }
}

// ================= tensor-core flash attention =================
// q-tile 64, kt-step 32, 256 threads. Q/K natural [t][h]; V pre-transposed [h][t].
// smem rows padded: Q/K 528 B (512 payload), Vt/P 80 B (64 payload).
#define AQH 0u
#define AQL 33792u
#define AKH(bf) (67584u + (uint32_t)(bf) * 33792u)
#define AKL(bf) (AKH(bf) + 16896u)
#define AVH 135168u
#define AVL 155648u
#define ASS 176128u
#define APH 186368u
#define APL 191488u
#define AMM 196608u
#define ALL 196864u
#define AAL 197120u
#define ATTN_SMEM 197632u

__global__ void __launch_bounds__(256, 1) attn_tc_kernel()
{
    extern __shared__ char smc[];
    const uint32_t sb = smem_u32(smc);
    float*  Ssm = (float*)(smc + ASS);
    __half* Phs = (__half*)(smc + APH);
    __half* Pls = (__half*)(smc + APL);
    float*  Msm = (float*)(smc + AMM);
    float*  Lsm = (float*)(smc + ALL);
    float*  Asm = (float*)(smc + AAL);

    const int tid = threadIdx.x, wid = tid >> 5, lane = tid & 31;
    const int gid = lane >> 2, tid2 = (lane & 3) * 2;
    const int l15 = lane & 15;
    const uint32_t lsel = (uint32_t)(lane >> 4) * 16u;
    const int wrow = (wid & 3) * 16;          // q rows
    const int wkey = (wid >> 2) * 16;         // key cols (QK)
    const int wcol = (wid >> 2) * 128;        // h cols (PV)

    const int qt0 = blockIdx.x * 64;
    const int bn  = blockIdx.y;
    const int b = bn / NQ_, n = bn % NQ_;
    const int kvh = n >> 1;

    if (tid < 64) { Msm[tid] = -1e30f; Lsm[tid] = 0.f; Asm[tid] = 1.f; }

    const size_t qbase  = ((size_t)(b*S_ + qt0) * NQ_ + n) * H_;
    const size_t kbase  = ((size_t)(b*S_) * NKV_ + kvh) * H_;
    const size_t vtbase = ((size_t)(b*NKV_ + kvh)) * H_ * S_;

    // prologue: Q + first K tile
#pragma unroll
    for (int p = 0; p < 8; p++) {
        int chunk = p * 256 + tid;
        int row = chunk >> 5, seg = chunk & 31;
        size_t off = qbase + (size_t)row * (NQ_*H_) + seg * 8;
        uint32_t d = sb + (uint32_t)(row * 528 + seg * 16);
        CP16(d + AQH, g_qh + off);
        CP16(d + AQL, g_ql + off);
    }
    int lo0 = qt0 - (WINDOW_ - 1); if (lo0 < 0) lo0 = 0;
    const int kt_lo = lo0 >> 5;
    const int kt_hi = (qt0 + 63) >> 5;
#pragma unroll
    for (int p = 0; p < 4; p++) {
        int chunk = p * 256 + tid;
        int row = chunk >> 5, seg = chunk & 31;
        size_t off = kbase + (size_t)(kt_lo * 32 + row) * (NKV_*H_) + seg * 8;
        uint32_t d = sb + (uint32_t)(row * 528 + seg * 16);
        CP16(d + AKH(0), g_kh + off);
        CP16(d + AKL(0), g_kl + off);
    }
    CPCOMMIT();

    float o[16][4];
#pragma unroll
    for (int nf = 0; nf < 16; nf++)
#pragma unroll
        for (int r = 0; r < 4; r++) o[nf][r] = 0.f;

    for (int kt = kt_lo; kt <= kt_hi; kt++) {
        const int buf = (kt - kt_lo) & 1;
        const int kt0 = kt * 32;
        CPWAIT0();
        __syncthreads();

        // issue V tile for this step
#pragma unroll
        for (int p = 0; p < 4; p++) {
            int chunk = p * 256 + tid;
            int row = chunk >> 2, seg = chunk & 3;
            size_t off = vtbase + (size_t)row * S_ + kt0 + seg * 8;
            uint32_t d = sb + (uint32_t)(row * 80 + seg * 16);
            CP16(d + AVH, g_vth + off);
            CP16(d + AVL, g_vtl + off);
        }
        CPCOMMIT();
        // prefetch next K tile
        if (kt < kt_hi) {
#pragma unroll
            for (int p = 0; p < 4; p++) {
                int chunk = p * 256 + tid;
                int row = chunk >> 5, seg = chunk & 31;
                size_t off = kbase + (size_t)(kt0 + 32 + row) * (NKV_*H_) + seg * 8;
                uint32_t d = sb + (uint32_t)(row * 528 + seg * 16);
                CP16(d + AKH(buf ^ 1), g_kh + off);
                CP16(d + AKL(buf ^ 1), g_kl + off);
            }
            CPCOMMIT();
        }

        // S = Q Kt (3-term)
        float acc[2][4];
#pragma unroll
        for (int nf = 0; nf < 2; nf++)
#pragma unroll
            for (int r = 0; r < 4; r++) acc[nf][r] = 0.f;
#pragma unroll
        for (int ks = 0; ks < 16; ks++) {
            const uint32_t cb = (uint32_t)(ks * 32) + lsel;
            uint32_t qh4[4], ql4[4], kh4[4], kl4[4];
            LDMX4(qh4, sb + AQH + (uint32_t)((wrow + l15) * 528) + cb);
            LDMX4(ql4, sb + AQL + (uint32_t)((wrow + l15) * 528) + cb);
            LDMX4(kh4, sb + AKH(buf) + (uint32_t)((wkey + l15) * 528) + cb);
            LDMX4(kl4, sb + AKL(buf) + (uint32_t)((wkey + l15) * 528) + cb);
#pragma unroll
            for (int nf = 0; nf < 2; nf++) {
                MMA16816(acc[nf], qh4, kh4[nf], kh4[2 + nf]);
                MMA16816(acc[nf], ql4, kh4[nf], kh4[2 + nf]);
                MMA16816(acc[nf], qh4, kl4[nf], kl4[2 + nf]);
            }
        }

        // cap + mask, stage S
#pragma unroll
        for (int nf = 0; nf < 2; nf++)
#pragma unroll
            for (int hh = 0; hh < 2; hh++)
#pragma unroll
                for (int jj = 0; jj < 2; jj++) {
                    const int rloc = wrow + gid + hh * 8;
                    const int cloc = wkey + nf * 8 + tid2 + jj;
                    const int tg = qt0 + rloc, sg = kt0 + cloc;
                    float v = acc[nf][hh * 2 + jj];
                    float xv = fminf(fmaxf(v * 0.02f, -15.f), 15.f);
                    float e = __expf(2.f * xv);
                    float lv = 50.f * (e - 1.f) / (e + 1.f);
                    if (sg > tg || sg <= tg - WINDOW_) lv = -1e30f;
                    Ssm[rloc * 40 + cloc] = lv;
                }
        __syncthreads();

        // softmax (thread: row tid>>2, 8 cols)
        {
            const int r = tid >> 2, c0 = (tid & 3) * 8;
            float s[8];
#pragma unroll
            for (int j = 0; j < 8; j++) s[j] = Ssm[r * 40 + c0 + j];
            float mx = s[0];
#pragma unroll
            for (int j = 1; j < 8; j++) mx = fmaxf(mx, s[j]);
            mx = fmaxf(mx, __shfl_xor_sync(0xffffffffu, mx, 1));
            mx = fmaxf(mx, __shfl_xor_sync(0xffffffffu, mx, 2));
            float mold = Msm[r];
            float mnew = fmaxf(mold, mx);
            float alpha = __expf(mold - mnew);
            float ls = 0.f, pv[8];
#pragma unroll
            for (int j = 0; j < 8; j++) {
                pv[j] = (s[j] > -1e29f) ? __expf(s[j] - mnew) : 0.f;
                ls += pv[j];
            }
            ls += __shfl_xor_sync(0xffffffffu, ls, 1);
            ls += __shfl_xor_sync(0xffffffffu, ls, 2);
            if ((tid & 3) == 0) {
                Lsm[r] = Lsm[r] * alpha + ls;
                Msm[r] = mnew;
                Asm[r] = alpha;
            }
#pragma unroll
            for (int j = 0; j < 8; j++) {
                __half h = __float2half_rn(pv[j]);
                Phs[r * 40 + c0 + j] = h;
                Pls[r * 40 + c0 + j] = __float2half_rn(pv[j] - __half2float(h));
            }
        }
        if (kt < kt_hi) { CPWAIT1(); } else { CPWAIT0(); }
        __syncthreads();

        // rescale O; O += P V (3-term)
        {
            float a0 = Asm[wrow + gid], a1 = Asm[wrow + gid + 8];
#pragma unroll
            for (int nf = 0; nf < 16; nf++) {
                o[nf][0] *= a0; o[nf][1] *= a0;
                o[nf][2] *= a1; o[nf][3] *= a1;
            }
        }
#pragma unroll
        for (int ks = 0; ks < 2; ks++) {
            const uint32_t cb = (uint32_t)(ks * 32) + lsel;
            uint32_t ph4[4], pl4[4];
            LDMX4(ph4, sb + APH + (uint32_t)((wrow + l15) * 80) + cb);
            LDMX4(pl4, sb + APL + (uint32_t)((wrow + l15) * 80) + cb);
#pragma unroll
            for (int ng = 0; ng < 8; ng++) {
                uint32_t vh4[4], vl4[4];
                const uint32_t vr = (uint32_t)((wcol + ng * 16 + l15) * 80) + cb;
                LDMX4(vh4, sb + AVH + vr);
                LDMX4(vl4, sb + AVL + vr);
#pragma unroll
                for (int h2 = 0; h2 < 2; h2++) {
                    const int nf = ng * 2 + h2;
                    MMA16816(o[nf], ph4, vh4[h2], vh4[2 + h2]);
                    MMA16816(o[nf], pl4, vh4[h2], vh4[2 + h2]);
                    MMA16816(o[nf], ph4, vl4[h2], vl4[2 + h2]);
                }
            }
        }
    }

    // normalize + split-write av
    {
        float inv0 = 1.f / Lsm[wrow + gid];
        float inv1 = 1.f / Lsm[wrow + gid + 8];
        size_t ob0 = ((size_t)(b*S_ + qt0 + wrow + gid) * NQ_ + n) * H_ + wcol;
        size_t ob1 = ob0 + (size_t)8 * NQ_ * H_;
#pragma unroll
        for (int nf = 0; nf < 16; nf++) {
            float f0 = o[nf][0] * inv0, f1 = o[nf][1] * inv0;
            float f2 = o[nf][2] * inv1, f3 = o[nf][3] * inv1;
            __half h0 = __float2half_rn(f0), h1 = __float2half_rn(f1);
            __half h2 = __float2half_rn(f2), h3 = __float2half_rn(f3);
            size_t c = (size_t)(nf * 8 + tid2);
            *(__half2*)(g_avh + ob0 + c) = __halves2half2(h0, h1);
            *(__half2*)(g_avl + ob0 + c) = __halves2half2(__float2half_rn(f0 - __half2float(h0)),
                                                          __float2half_rn(f1 - __half2float(h1)));
            *(__half2*)(g_avh + ob1 + c) = __halves2half2(h2, h3);
            *(__half2*)(g_avl + ob1 + c) = __halves2half2(__float2half_rn(f2 - __half2float(h2)),
                                                          __float2half_rn(f3 - __half2float(h3)));
        }
    }
}

// ---------------- launch ----------------
extern "C" void kernel_launch(void* const* d_in, const int* in_sizes, int n_in,
                              void* d_out, int out_size)
{
    const float* x  = (const float*)d_in[0];
    const float* Wq = (const float*)d_in[1];
    const float* Wk = (const float*)d_in[2];
    const float* Wv = (const float*)d_in[3];
    const float* Wo = (const float*)d_in[4];
    float* out = (float*)d_out;

    float *q, *k, *v;
    cudaGetSymbolAddress((void**)&q, g_q);
    cudaGetSymbolAddress((void**)&k, g_k);
    cudaGetSymbolAddress((void**)&v, g_v);
    __half *xh, *xl, *wqh, *wql, *wkh, *wkl, *wvh, *wvl, *woh, *wol, *avh, *avl;
    __half *qh, *ql, *kh, *kl;
    cudaGetSymbolAddress((void**)&xh,  g_xh);  cudaGetSymbolAddress((void**)&xl,  g_xl);
    cudaGetSymbolAddress((void**)&wqh, g_wqh); cudaGetSymbolAddress((void**)&wql, g_wql);
    cudaGetSymbolAddress((void**)&wkh, g_wkh); cudaGetSymbolAddress((void**)&wkl, g_wkl);
    cudaGetSymbolAddress((void**)&wvh, g_wvh); cudaGetSymbolAddress((void**)&wvl, g_wvl);
    cudaGetSymbolAddress((void**)&woh, g_woh); cudaGetSymbolAddress((void**)&wol, g_wol);
    cudaGetSymbolAddress((void**)&avh, g_avh); cudaGetSymbolAddress((void**)&avl, g_avl);
    cudaGetSymbolAddress((void**)&qh,  g_qh);  cudaGetSymbolAddress((void**)&ql,  g_ql);
    cudaGetSymbolAddress((void**)&kh,  g_kh);  cudaGetSymbolAddress((void**)&kl,  g_kl);

    const int M = B_ * S_;   // 4096

    cudaFuncSetAttribute(hgemm_kernel<2>, cudaFuncAttributeMaxDynamicSharedMemorySize, 98304);
    cudaFuncSetAttribute(hgemm_kernel<3>, cudaFuncAttributeMaxDynamicSharedMemorySize, 131072);
    cudaFuncSetAttribute(attn_tc_kernel, cudaFuncAttributeMaxDynamicSharedMemorySize, ATTN_SMEM);

    // conversions
    {
        int n4 = M * D_ / 4;
        convert_split_kernel<<<(n4 + 255) / 256, 256>>>(x, xh, xl, n4);
    }
    convert_wt_kernel<<<dim3(H_/32, D_/32, NQ_),  dim3(32, 8)>>>(Wq, wqh, wql, D_, H_);
    convert_wt_kernel<<<dim3(H_/32, D_/32, NKV_), dim3(32, 8)>>>(Wk, wkh, wkl, D_, H_);
    convert_wt_kernel<<<dim3(H_/32, D_/32, NKV_), dim3(32, 8)>>>(Wv, wvh, wvl, D_, H_);
    convert_wt_kernel<<<dim3(D_/32, (NQ_*H_)/32, 1), dim3(32, 8)>>>(Wo, woh, wol, NQ_*H_, D_);

    // QKV projections (2-term)
    hgemm_kernel<2><<<dim3(H_/128, M/128, NQ_),  256, 98304>>>(
        xh, xl, D_, wqh, wql, (long long)H_ * D_, q, NQ_*H_, H_);
    hgemm_kernel<2><<<dim3(H_/128, M/128, NKV_), 256, 98304>>>(
        xh, xl, D_, wkh, wkl, (long long)H_ * D_, k, NKV_*H_, H_);
    hgemm_kernel<2><<<dim3(H_/128, M/128, NKV_), 256, 98304>>>(
        xh, xl, D_, wvh, wvl, (long long)H_ * D_, v, NKV_*H_, H_);

    // rope + split, V transpose + split
    rope_split_kernel<<<M * NQ_,  128>>>(q, qh, ql, NQ_,  0.0625f);
    rope_split_kernel<<<M * NKV_, 128>>>(k, kh, kl, NKV_, 1.0f);
    vtrans_kernel<<<dim3(S_/32, H_/32, B_*NKV_), dim3(32, 8)>>>();

    // attention
    attn_tc_kernel<<<dim3(S_/64, B_*NQ_), 256, ATTN_SMEM>>>();

    // output projection (3-term)
    hgemm_kernel<3><<<dim3(D_/128, M/128, 1), 256, 131072>>>(
        avh, avl, NQ_*H_, woh, wol, 0, out, D_, 0);
}

// round 11
// speedup vs baseline: 4.0463x; 1.1765x over previous
#include <cuda_runtime.h>
#include <cuda_fp16.h>
#include <cstdint>
#include <math.h>

#define B_     2
#define S_     2048
#define D_     2048
#define NQ_    16
#define NKV_   8
#define H_     256
#define WINDOW_ 1024

// ---------------- scratch (device globals; no allocation) ----------------
__device__ float g_q [B_*S_*NQ_ *H_];
__device__ float g_k [B_*S_*NKV_*H_];
__device__ float g_v [B_*S_*NKV_*H_];

__device__ __half g_xh [4096*2048];
__device__ __half g_xl [4096*2048];
__device__ __half g_wqh[16*256*2048];
__device__ __half g_wkh[8*256*2048];
__device__ __half g_wvh[8*256*2048];
__device__ __half g_woh[2048*4096];
__device__ __half g_avh[4096*4096];
__device__ __half g_avl[4096*4096];
__device__ __half g_qh [B_*S_*NQ_ *H_];
__device__ __half g_ql [B_*S_*NQ_ *H_];
__device__ __half g_kh [B_*S_*NKV_*H_];
__device__ __half g_vth[B_*NKV_*H_*S_];   // [b][kvh][h][t]

// ---------------- helpers ----------------
__device__ __forceinline__ uint32_t smem_u32(const void* p) {
    uint32_t a;
    asm("{ .reg .u64 t; cvta.to.shared.u64 t, %1; cvt.u32.u64 %0, t; }" : "=r"(a) : "l"(p));
    return a;
}
#define MMA16816(c, a, b0, b1)                                               \
    asm volatile("mma.sync.aligned.m16n8k16.row.col.f32.f16.f16.f32 "        \
        "{%0,%1,%2,%3}, {%4,%5,%6,%7}, {%8,%9}, {%0,%1,%2,%3};"              \
        : "+f"((c)[0]), "+f"((c)[1]), "+f"((c)[2]), "+f"((c)[3])             \
        : "r"((a)[0]), "r"((a)[1]), "r"((a)[2]), "r"((a)[3]), "r"(b0), "r"(b1))
#define LDMX4(d, addr)                                                       \
    asm volatile("ldmatrix.sync.aligned.m8n8.x4.shared.b16 {%0,%1,%2,%3}, [%4];" \
        : "=r"((d)[0]), "=r"((d)[1]), "=r"((d)[2]), "=r"((d)[3]) : "r"(addr))
#define CP16(dst, src)                                                       \
    asm volatile("cp.async.cg.shared.global [%0], [%1], 16;" :: "r"(dst), "l"(src))
#define CPCOMMIT() asm volatile("cp.async.commit_group;" ::: "memory")
#define CPWAIT0()  asm volatile("cp.async.wait_group 0;" ::: "memory")
#define CPWAIT1()  asm volatile("cp.async.wait_group 1;" ::: "memory")
#define SWZ(byte) ((byte) ^ (((byte) >> 3) & 0x70))

// ---------------- fp32 -> (hi, lo) fp16 elementwise ----------------
__global__ void __launch_bounds__(256) convert_split_kernel(
    const float* __restrict__ src, __half* __restrict__ hi, __half* __restrict__ lo, int n4)
{
    int idx = blockIdx.x * 256 + threadIdx.x;
    if (idx >= n4) return;
    float4 v = ((const float4*)src)[idx];
    __half h0 = __float2half_rn(v.x), h1 = __float2half_rn(v.y);
    __half h2 = __float2half_rn(v.z), h3 = __float2half_rn(v.w);
    ((__half2*)hi)[idx*2]   = __halves2half2(h0, h1);
    ((__half2*)hi)[idx*2+1] = __halves2half2(h2, h3);
    ((__half2*)lo)[idx*2]   = __halves2half2(__float2half_rn(v.x - __half2float(h0)),
                                             __float2half_rn(v.y - __half2float(h1)));
    ((__half2*)lo)[idx*2+1] = __halves2half2(__float2half_rn(v.z - __half2float(h2)),
                                             __float2half_rn(v.w - __half2float(h3)));
}

// ---------------- weight transpose (hi only): [z][K][N] -> [z][N][K] ----------------
__global__ void __launch_bounds__(256) convert_wt_hi_kernel(
    const float* __restrict__ src, __half* __restrict__ hi, int K, int N)
{
    __shared__ float t[32][33];
    const int z = blockIdx.z;
    const float* s = src + (long long)z * K * N;
    __half* hz = hi + (long long)z * K * N;
    const int n0 = blockIdx.x * 32, k0 = blockIdx.y * 32;
    const int x = threadIdx.x, y = threadIdx.y;
#pragma unroll
    for (int i = 0; i < 4; i++)
        t[y + 8*i][x] = s[(long long)(k0 + y + 8*i) * N + n0 + x];
    __syncthreads();
#pragma unroll
    for (int i = 0; i < 4; i++)
        hz[(long long)(n0 + y + 8*i) * K + k0 + x] = __float2half_rn(t[x][y + 8*i]);
}

// ---------------- V transpose (hi only) ----------------
__global__ void __launch_bounds__(256) vtrans_kernel()
{
    __shared__ float t[32][33];
    const int z = blockIdx.z;            // b*NKV + kvh
    const int b = z / NKV_, kvh = z % NKV_;
    const int t0 = blockIdx.x * 32, h0 = blockIdx.y * 32;
    const int x = threadIdx.x, y = threadIdx.y;
#pragma unroll
    for (int i = 0; i < 4; i++)
        t[x][y + 8*i] = g_v[(((long long)(b*S_ + t0 + x)) * NKV_ + kvh) * H_ + h0 + y + 8*i];
    __syncthreads();
    const long long obase = ((long long)z * H_) * S_;
#pragma unroll
    for (int i = 0; i < 4; i++)
        g_vth[obase + (long long)(h0 + y + 8*i) * S_ + t0 + x] = __float2half_rn(t[x][y + 8*i]);
}

// ---------------- RoPE + split (q: hi+lo) ----------------
__global__ void rope_split_kernel(const float* __restrict__ src,
                                  __half* __restrict__ hi, __half* __restrict__ lo,
                                  int nheads, float scale)
{
    long long bid = blockIdx.x;
    int t = (int)((bid / nheads) % S_);
    int i = threadIdx.x;
    const float* p = src + bid * H_;
    float x1 = p[i], x2 = p[i + 128];
    float ex = (float)(2*i) * (1.0f / (float)H_);
    float inv_freq = powf(10000.0f, -ex);
    float ff = (float)t * inv_freq;
    double fr = (double)ff;
    const double TWO_PI = 6.283185307179586476925286766559;
    fr = fr - floor(fr / TWO_PI) * TWO_PI;
    float c = cosf((float)fr), s = sinf((float)fr);
    float r1 = (x1 * c - x2 * s) * scale;
    float r2 = (x2 * c + x1 * s) * scale;
    __half h1 = __float2half_rn(r1), h2 = __float2half_rn(r2);
    hi[bid*H_ + 2*i]   = h1;
    hi[bid*H_ + 2*i+1] = h2;
    lo[bid*H_ + 2*i]   = __float2half_rn(r1 - __half2float(h1));
    lo[bid*H_ + 2*i+1] = __float2half_rn(r2 - __half2float(h2));
}

// ---------------- RoPE (hi only, for k) ----------------
__global__ void rope_hi_kernel(const float* __restrict__ src,
                               __half* __restrict__ hi, int nheads, float scale)
{
    long long bid = blockIdx.x;
    int t = (int)((bid / nheads) % S_);
    int i = threadIdx.x;
    const float* p = src + bid * H_;
    float x1 = p[i], x2 = p[i + 128];
    float ex = (float)(2*i) * (1.0f / (float)H_);
    float inv_freq = powf(10000.0f, -ex);
    float ff = (float)t * inv_freq;
    double fr = (double)ff;
    const double TWO_PI = 6.283185307179586476925286766559;
    fr = fr - floor(fr / TWO_PI) * TWO_PI;
    float c = cosf((float)fr), s = sinf((float)fr);
    hi[bid*H_ + 2*i]   = __float2half_rn((x1 * c - x2 * s) * scale);
    hi[bid*H_ + 2*i+1] = __float2half_rn((x2 * c + x1 * s) * scale);
}

// ================= split-fp16 GEMM, 2-term: (Ah+Al) x Bh =================
__global__ void __launch_bounds__(256, 1)
hgemm2_kernel(const __half* __restrict__ Ah, const __half* __restrict__ Al, int K,
              const __half* __restrict__ Bh,
              long long bZStride, float* __restrict__ C, int ldc, int cZStride)
{
    constexpr uint32_t AHI = 0, ALO = 16384, BHI = 32768;
    constexpr uint32_t STAGE = 49152u;
    extern __shared__ __half hsm[];
    const uint32_t sb = smem_u32(hsm);

    const int tid = threadIdx.x, wid = tid >> 5, lane = tid & 31;
    const int gid = lane >> 2, tid2 = (lane & 3) * 2;
    const int warpM = wid & 3, warpN = wid >> 2;
    const int lrow = lane & 15, lsel = lane >> 4;

    const int m0 = blockIdx.y * 128, n0 = blockIdx.x * 128, z = blockIdx.z;
    const __half* Bhp = Bh + (long long)z * bZStride;

    float acc[2][8][4];
#pragma unroll
    for (int mt = 0; mt < 2; mt++)
#pragma unroll
        for (int nf = 0; nf < 8; nf++)
#pragma unroll
            for (int r = 0; r < 4; r++) acc[mt][nf][r] = 0.f;

    const int nSlab = K >> 6;

#define FILLG(stage, s) do {                                                  \
    const int k0f = (s) << 6;                                                 \
    const uint32_t stBase = sb + (uint32_t)(stage) * STAGE;                   \
    _Pragma("unroll")                                                         \
    for (int p = 0; p < 4; p++) {                                             \
        const int chunk = p * 256 + tid;                                      \
        const int row = chunk >> 3, c16 = chunk & 7;                          \
        const uint32_t swz = SWZ((uint32_t)(row * 128 + c16 * 16));           \
        const long long ka = (long long)(m0 + row) * K + k0f + c16 * 8;       \
        const long long kb = (long long)(n0 + row) * K + k0f + c16 * 8;       \
        CP16(stBase + AHI + swz, Ah + ka);                                    \
        CP16(stBase + ALO + swz, Al + ka);                                    \
        CP16(stBase + BHI + swz, Bhp + kb);                                   \
    }                                                                         \
    CPCOMMIT();                                                               \
} while (0)

    FILLG(0, 0);
    for (int s = 0; s < nSlab; s++) {
        CPWAIT0();
        __syncthreads();
        if (s + 1 < nSlab) FILLG((s + 1) & 1, s + 1);

        const uint32_t stBase = sb + (uint32_t)(s & 1) * STAGE;
#pragma unroll
        for (int ks = 0; ks < 4; ks++) {
            const int ck = ks * 2 + lsel;
            uint32_t ah[2][4], al[2][4], bh[4][4];
#pragma unroll
            for (int mt = 0; mt < 2; mt++) {
                const int row = warpM * 32 + mt * 16 + lrow;
                const uint32_t swz = SWZ((uint32_t)(row * 128 + ck * 16));
                LDMX4(ah[mt], stBase + AHI + swz);
                LDMX4(al[mt], stBase + ALO + swz);
            }
#pragma unroll
            for (int ng = 0; ng < 4; ng++) {
                const int row = warpN * 64 + ng * 16 + lrow;
                const uint32_t swz = SWZ((uint32_t)(row * 128 + ck * 16));
                LDMX4(bh[ng], stBase + BHI + swz);
            }
#pragma unroll
            for (int ng = 0; ng < 4; ng++)
#pragma unroll
                for (int h = 0; h < 2; h++) {
                    const int nf = ng * 2 + h;
#pragma unroll
                    for (int mt = 0; mt < 2; mt++) {
                        MMA16816(acc[mt][nf], ah[mt], bh[ng][h], bh[ng][2 + h]);
                        MMA16816(acc[mt][nf], al[mt], bh[ng][h], bh[ng][2 + h]);
                    }
                }
        }
    }
#undef FILLG

#pragma unroll
    for (int mt = 0; mt < 2; mt++) {
        const int row0 = m0 + warpM * 32 + mt * 16 + gid;
#pragma unroll
        for (int nf = 0; nf < 8; nf++) {
            const int col = z * cZStride + n0 + warpN * 64 + nf * 8 + tid2;
            *(float2*)(C + (long long)row0 * ldc + col) =
                make_float2(acc[mt][nf][0], acc[mt][nf][1]);
            *(float2*)(C + (long long)(row0 + 8) * ldc + col) =
                make_float2(acc[mt][nf][2], acc[mt][nf][3]);
        }
    }
}

// ================= tensor-core flash attention (2-term QK and PV) =================
// q-tile 64, kt-step 32, 256 threads. Q/K natural [t][h]; V pre-transposed [h][t].
// smem rows padded: Q/K 528 B (512 payload), Vt/P 80 B (64 payload).
#define AQH 0u
#define AQL 33792u
#define AKH(bf) (67584u + (uint32_t)(bf) * 16896u)
#define AVH 101376u
#define ASS 121856u
#define APH 132096u
#define APL 137216u
#define AMM 142336u
#define ALL 142592u
#define AAL 142848u
#define ATTN_SMEM 143104u

__global__ void __launch_bounds__(256, 1) attn_tc_kernel()
{
    extern __shared__ char smc[];
    const uint32_t sb = smem_u32(smc);
    float*  Ssm = (float*)(smc + ASS);
    __half* Phs = (__half*)(smc + APH);
    __half* Pls = (__half*)(smc + APL);
    float*  Msm = (float*)(smc + AMM);
    float*  Lsm = (float*)(smc + ALL);
    float*  Asm = (float*)(smc + AAL);

    const int tid = threadIdx.x, wid = tid >> 5, lane = tid & 31;
    const int gid = lane >> 2, tid2 = (lane & 3) * 2;
    const int l15 = lane & 15;
    const uint32_t lsel = (uint32_t)(lane >> 4) * 16u;
    const int wrow = (wid & 3) * 16;          // q rows
    const int wkey = (wid >> 2) * 16;         // key cols (QK)
    const int wcol = (wid >> 2) * 128;        // h cols (PV)

    const int qt0 = blockIdx.x * 64;
    const int bn  = blockIdx.y;
    const int b = bn / NQ_, n = bn % NQ_;
    const int kvh = n >> 1;

    if (tid < 64) { Msm[tid] = -1e30f; Lsm[tid] = 0.f; Asm[tid] = 1.f; }

    const size_t qbase  = ((size_t)(b*S_ + qt0) * NQ_ + n) * H_;
    const size_t kbase  = ((size_t)(b*S_) * NKV_ + kvh) * H_;
    const size_t vtbase = ((size_t)(b*NKV_ + kvh)) * H_ * S_;

    // prologue: Q + first K tile
#pragma unroll
    for (int p = 0; p < 8; p++) {
        int chunk = p * 256 + tid;
        int row = chunk >> 5, seg = chunk & 31;
        size_t off = qbase + (size_t)row * (NQ_*H_) + seg * 8;
        uint32_t d = sb + (uint32_t)(row * 528 + seg * 16);
        CP16(d + AQH, g_qh + off);
        CP16(d + AQL, g_ql + off);
    }
    int lo0 = qt0 - (WINDOW_ - 1); if (lo0 < 0) lo0 = 0;
    const int kt_lo = lo0 >> 5;
    const int kt_hi = (qt0 + 63) >> 5;
#pragma unroll
    for (int p = 0; p < 2; p++) {
        int chunk = p * 256 + tid;
        int row = chunk >> 4, seg = chunk & 15;
        size_t off = kbase + (size_t)(kt_lo * 32 + row) * (NKV_*H_) + seg * 16;
        uint32_t d = sb + (uint32_t)(row * 528 + seg * 32);
        CP16(d + AKH(0), g_kh + off);
        CP16(d + AKH(0) + 16u, g_kh + off + 8);
    }
    CPCOMMIT();

    float o[16][4];
#pragma unroll
    for (int nf = 0; nf < 16; nf++)
#pragma unroll
        for (int r = 0; r < 4; r++) o[nf][r] = 0.f;

    for (int kt = kt_lo; kt <= kt_hi; kt++) {
        const int buf = (kt - kt_lo) & 1;
        const int kt0 = kt * 32;
        CPWAIT0();
        __syncthreads();

        // issue V tile for this step (hi only)
#pragma unroll
        for (int p = 0; p < 2; p++) {
            int chunk = p * 256 + tid;
            int row = chunk >> 1, seg = chunk & 1;
            size_t off = vtbase + (size_t)row * S_ + kt0 + seg * 16;
            uint32_t d = sb + (uint32_t)(row * 80 + seg * 32);
            CP16(d + AVH, g_vth + off);
            CP16(d + AVH + 16u, g_vth + off + 8);
        }
        CPCOMMIT();
        // prefetch next K tile
        if (kt < kt_hi) {
#pragma unroll
            for (int p = 0; p < 2; p++) {
                int chunk = p * 256 + tid;
                int row = chunk >> 4, seg = chunk & 15;
                size_t off = kbase + (size_t)(kt0 + 32 + row) * (NKV_*H_) + seg * 16;
                uint32_t d = sb + (uint32_t)(row * 528 + seg * 32);
                CP16(d + AKH(buf ^ 1), g_kh + off);
                CP16(d + AKH(buf ^ 1) + 16u, g_kh + off + 8);
            }
            CPCOMMIT();
        }

        // S = Q Kt (2-term)
        float acc[2][4];
#pragma unroll
        for (int nf = 0; nf < 2; nf++)
#pragma unroll
            for (int r = 0; r < 4; r++) acc[nf][r] = 0.f;
#pragma unroll
        for (int ks = 0; ks < 16; ks++) {
            const uint32_t cb = (uint32_t)(ks * 32) + lsel;
            uint32_t qh4[4], ql4[4], kh4[4];
            LDMX4(qh4, sb + AQH + (uint32_t)((wrow + l15) * 528) + cb);
            LDMX4(ql4, sb + AQL + (uint32_t)((wrow + l15) * 528) + cb);
            LDMX4(kh4, sb + AKH(buf) + (uint32_t)((wkey + l15) * 528) + cb);
#pragma unroll
            for (int nf = 0; nf < 2; nf++) {
                MMA16816(acc[nf], qh4, kh4[nf], kh4[2 + nf]);
                MMA16816(acc[nf], ql4, kh4[nf], kh4[2 + nf]);
            }
        }

        // cap + mask, stage S
#pragma unroll
        for (int nf = 0; nf < 2; nf++)
#pragma unroll
            for (int hh = 0; hh < 2; hh++)
#pragma unroll
                for (int jj = 0; jj < 2; jj++) {
                    const int rloc = wrow + gid + hh * 8;
                    const int cloc = wkey + nf * 8 + tid2 + jj;
                    const int tg = qt0 + rloc, sg = kt0 + cloc;
                    float v = acc[nf][hh * 2 + jj];
                    float xv = fminf(fmaxf(v * 0.02f, -15.f), 15.f);
                    float e = __expf(2.f * xv);
                    float lv = 50.f * (e - 1.f) / (e + 1.f);
                    if (sg > tg || sg <= tg - WINDOW_) lv = -1e30f;
                    Ssm[rloc * 40 + cloc] = lv;
                }
        __syncthreads();

        // softmax (thread: row tid>>2, 8 cols)
        {
            const int r = tid >> 2, c0 = (tid & 3) * 8;
            float s[8];
#pragma unroll
            for (int j = 0; j < 8; j++) s[j] = Ssm[r * 40 + c0 + j];
            float mx = s[0];
#pragma unroll
            for (int j = 1; j < 8; j++) mx = fmaxf(mx, s[j]);
            mx = fmaxf(mx, __shfl_xor_sync(0xffffffffu, mx, 1));
            mx = fmaxf(mx, __shfl_xor_sync(0xffffffffu, mx, 2));
            float mold = Msm[r];
            float mnew = fmaxf(mold, mx);
            float alpha = __expf(mold - mnew);
            float ls = 0.f, pv[8];
#pragma unroll
            for (int j = 0; j < 8; j++) {
                pv[j] = (s[j] > -1e29f) ? __expf(s[j] - mnew) : 0.f;
                ls += pv[j];
            }
            ls += __shfl_xor_sync(0xffffffffu, ls, 1);
            ls += __shfl_xor_sync(0xffffffffu, ls, 2);
            if ((tid & 3) == 0) {
                Lsm[r] = Lsm[r] * alpha + ls;
                Msm[r] = mnew;
                Asm[r] = alpha;
            }
#pragma unroll
            for (int j = 0; j < 8; j++) {
                __half h = __float2half_rn(pv[j]);
                Phs[r * 40 + c0 + j] = h;
                Pls[r * 40 + c0 + j] = __float2half_rn(pv[j] - __half2float(h));
            }
        }
        if (kt < kt_hi) { CPWAIT1(); } else { CPWAIT0(); }
        __syncthreads();

        // rescale O; O += P V (2-term)
        {
            float a0 = Asm[wrow + gid], a1 = Asm[wrow + gid + 8];
#pragma unroll
            for (int nf = 0; nf < 16; nf++) {
                o[nf][0] *= a0; o[nf][1] *= a0;
                o[nf][2] *= a1; o[nf][3] *= a1;
            }
        }
#pragma unroll
        for (int ks = 0; ks < 2; ks++) {
            const uint32_t cb = (uint32_t)(ks * 32) + lsel;
            uint32_t ph4[4], pl4[4];
            LDMX4(ph4, sb + APH + (uint32_t)((wrow + l15) * 80) + cb);
            LDMX4(pl4, sb + APL + (uint32_t)((wrow + l15) * 80) + cb);
#pragma unroll
            for (int ng = 0; ng < 8; ng++) {
                uint32_t vh4[4];
                const uint32_t vr = (uint32_t)((wcol + ng * 16 + l15) * 80) + cb;
                LDMX4(vh4, sb + AVH + vr);
#pragma unroll
                for (int h2 = 0; h2 < 2; h2++) {
                    const int nf = ng * 2 + h2;
                    MMA16816(o[nf], ph4, vh4[h2], vh4[2 + h2]);
                    MMA16816(o[nf], pl4, vh4[h2], vh4[2 + h2]);
                }
            }
        }
    }

    // normalize + split-write av
    {
        float inv0 = 1.f / Lsm[wrow + gid];
        float inv1 = 1.f / Lsm[wrow + gid + 8];
        size_t ob0 = ((size_t)(b*S_ + qt0 + wrow + gid) * NQ_ + n) * H_ + wcol;
        size_t ob1 = ob0 + (size_t)8 * NQ_ * H_;
#pragma unroll
        for (int nf = 0; nf < 16; nf++) {
            float f0 = o[nf][0] * inv0, f1 = o[nf][1] * inv0;
            float f2 = o[nf][2] * inv1, f3 = o[nf][3] * inv1;
            __half h0 = __float2half_rn(f0), h1 = __float2half_rn(f1);
            __half h2 = __float2half_rn(f2), h3 = __float2half_rn(f3);
            size_t c = (size_t)(nf * 8 + tid2);
            *(__half2*)(g_avh + ob0 + c) = __halves2half2(h0, h1);
            *(__half2*)(g_avl + ob0 + c) = __halves2half2(__float2half_rn(f0 - __half2float(h0)),
                                                          __float2half_rn(f1 - __half2float(h1)));
            *(__half2*)(g_avh + ob1 + c) = __halves2half2(h2, h3);
            *(__half2*)(g_avl + ob1 + c) = __halves2half2(__float2half_rn(f2 - __half2float(h2)),
                                                          __float2half_rn(f3 - __half2float(h3)));
        }
    }
}

// ---------------- launch ----------------
extern "C" void kernel_launch(void* const* d_in, const int* in_sizes, int n_in,
                              void* d_out, int out_size)
{
    const float* x  = (const float*)d_in[0];
    const float* Wq = (const float*)d_in[1];
    const float* Wk = (const float*)d_in[2];
    const float* Wv = (const float*)d_in[3];
    const float* Wo = (const float*)d_in[4];
    float* out = (float*)d_out;

    float *q, *k, *v;
    cudaGetSymbolAddress((void**)&q, g_q);
    cudaGetSymbolAddress((void**)&k, g_k);
    cudaGetSymbolAddress((void**)&v, g_v);
    __half *xh, *xl, *wqh, *wkh, *wvh, *woh, *avh, *avl, *qh, *ql, *kh;
    cudaGetSymbolAddress((void**)&xh,  g_xh);  cudaGetSymbolAddress((void**)&xl,  g_xl);
    cudaGetSymbolAddress((void**)&wqh, g_wqh);
    cudaGetSymbolAddress((void**)&wkh, g_wkh);
    cudaGetSymbolAddress((void**)&wvh, g_wvh);
    cudaGetSymbolAddress((void**)&woh, g_woh);
    cudaGetSymbolAddress((void**)&avh, g_avh); cudaGetSymbolAddress((void**)&avl, g_avl);
    cudaGetSymbolAddress((void**)&qh,  g_qh);  cudaGetSymbolAddress((void**)&ql,  g_ql);
    cudaGetSymbolAddress((void**)&kh,  g_kh);

    const int M = B_ * S_;   // 4096

    cudaFuncSetAttribute(hgemm2_kernel, cudaFuncAttributeMaxDynamicSharedMemorySize, 98304);
    cudaFuncSetAttribute(attn_tc_kernel, cudaFuncAttributeMaxDynamicSharedMemorySize, ATTN_SMEM);

    // conversions
    {
        int n4 = M * D_ / 4;
        convert_split_kernel<<<(n4 + 255) / 256, 256>>>(x, xh, xl, n4);
    }
    convert_wt_hi_kernel<<<dim3(H_/32, D_/32, NQ_),  dim3(32, 8)>>>(Wq, wqh, D_, H_);
    convert_wt_hi_kernel<<<dim3(H_/32, D_/32, NKV_), dim3(32, 8)>>>(Wk, wkh, D_, H_);
    convert_wt_hi_kernel<<<dim3(H_/32, D_/32, NKV_), dim3(32, 8)>>>(Wv, wvh, D_, H_);
    convert_wt_hi_kernel<<<dim3(D_/32, (NQ_*H_)/32, 1), dim3(32, 8)>>>(Wo, woh, NQ_*H_, D_);

    // QKV projections (2-term)
    hgemm2_kernel<<<dim3(H_/128, M/128, NQ_),  256, 98304>>>(
        xh, xl, D_, wqh, (long long)H_ * D_, q, NQ_*H_, H_);
    hgemm2_kernel<<<dim3(H_/128, M/128, NKV_), 256, 98304>>>(
        xh, xl, D_, wkh, (long long)H_ * D_, k, NKV_*H_, H_);
    hgemm2_kernel<<<dim3(H_/128, M/128, NKV_), 256, 98304>>>(
        xh, xl, D_, wvh, (long long)H_ * D_, v, NKV_*H_, H_);

    // rope + split, V transpose
    rope_split_kernel<<<M * NQ_,  128>>>(q, qh, ql, NQ_,  0.0625f);
    rope_hi_kernel<<<M * NKV_, 128>>>(k, kh, NKV_, 1.0f);
    vtrans_kernel<<<dim3(S_/32, H_/32, B_*NKV_), dim3(32, 8)>>>();

    // attention
    attn_tc_kernel<<<dim3(S_/64, B_*NQ_), 256, ATTN_SMEM>>>();

    // output projection (2-term)
    hgemm2_kernel<<<dim3(D_/128, M/128, 1), 256, 98304>>>(
        avh, avl, NQ_*H_, woh, 0, out, D_, 0);
}

// round 12
// speedup vs baseline: 6.2342x; 1.5407x over previous
#include <cuda_runtime.h>
#include <cuda_fp16.h>
#include <cstdint>
#include <math.h>

#define B_     2
#define S_     2048
#define D_     2048
#define NQ_    16
#define NKV_   8
#define H_     256
#define WINDOW_ 1024

// ---------------- scratch (device globals; no allocation) ----------------
__device__ float g_q [B_*S_*NQ_ *H_];
__device__ float g_k [B_*S_*NKV_*H_];
__device__ float g_v [B_*S_*NKV_*H_];

__device__ __half g_xh [4096*2048];
__device__ __half g_wqh[16*256*2048];
__device__ __half g_wkh[8*256*2048];
__device__ __half g_wvh[8*256*2048];
__device__ __half g_woh[2048*4096];
__device__ __half g_avh[4096*4096];
__device__ __half g_qh [B_*S_*NQ_ *H_];
__device__ __half g_kh [B_*S_*NKV_*H_];
__device__ __half g_vth[B_*NKV_*H_*S_];   // [b][kvh][h][t]

// ---------------- helpers ----------------
__device__ __forceinline__ uint32_t smem_u32(const void* p) {
    uint32_t a;
    asm("{ .reg .u64 t; cvta.to.shared.u64 t, %1; cvt.u32.u64 %0, t; }" : "=r"(a) : "l"(p));
    return a;
}
#define MMA16816(c, a, b0, b1)                                               \
    asm volatile("mma.sync.aligned.m16n8k16.row.col.f32.f16.f16.f32 "        \
        "{%0,%1,%2,%3}, {%4,%5,%6,%7}, {%8,%9}, {%0,%1,%2,%3};"              \
        : "+f"((c)[0]), "+f"((c)[1]), "+f"((c)[2]), "+f"((c)[3])             \
        : "r"((a)[0]), "r"((a)[1]), "r"((a)[2]), "r"((a)[3]), "r"(b0), "r"(b1))
#define LDMX4(d, addr)                                                       \
    asm volatile("ldmatrix.sync.aligned.m8n8.x4.shared.b16 {%0,%1,%2,%3}, [%4];" \
        : "=r"((d)[0]), "=r"((d)[1]), "=r"((d)[2]), "=r"((d)[3]) : "r"(addr))
#define CP16(dst, src)                                                       \
    asm volatile("cp.async.cg.shared.global [%0], [%1], 16;" :: "r"(dst), "l"(src))
#define CPCOMMIT() asm volatile("cp.async.commit_group;" ::: "memory")
#define CPWAIT0()  asm volatile("cp.async.wait_group 0;" ::: "memory")
#define CPWAIT1()  asm volatile("cp.async.wait_group 1;" ::: "memory")
#define SWZ(byte) ((byte) ^ (((byte) >> 3) & 0x70))

// ---------------- fp32 -> fp16 elementwise ----------------
__global__ void __launch_bounds__(256) convert_hi_kernel(
    const float* __restrict__ src, __half* __restrict__ hi, int n4)
{
    int idx = blockIdx.x * 256 + threadIdx.x;
    if (idx >= n4) return;
    float4 v = ((const float4*)src)[idx];
    ((__half2*)hi)[idx*2]   = __halves2half2(__float2half_rn(v.x), __float2half_rn(v.y));
    ((__half2*)hi)[idx*2+1] = __halves2half2(__float2half_rn(v.z), __float2half_rn(v.w));
}

// ---------------- weight transpose (hi only): [z][K][N] -> [z][N][K] ----------------
__global__ void __launch_bounds__(256) convert_wt_hi_kernel(
    const float* __restrict__ src, __half* __restrict__ hi, int K, int N)
{
    __shared__ float t[32][33];
    const int z = blockIdx.z;
    const float* s = src + (long long)z * K * N;
    __half* hz = hi + (long long)z * K * N;
    const int n0 = blockIdx.x * 32, k0 = blockIdx.y * 32;
    const int x = threadIdx.x, y = threadIdx.y;
#pragma unroll
    for (int i = 0; i < 4; i++)
        t[y + 8*i][x] = s[(long long)(k0 + y + 8*i) * N + n0 + x];
    __syncthreads();
#pragma unroll
    for (int i = 0; i < 4; i++)
        hz[(long long)(n0 + y + 8*i) * K + k0 + x] = __float2half_rn(t[x][y + 8*i]);
}

// ---------------- V transpose (hi only) ----------------
__global__ void __launch_bounds__(256) vtrans_kernel()
{
    __shared__ float t[32][33];
    const int z = blockIdx.z;            // b*NKV + kvh
    const int b = z / NKV_, kvh = z % NKV_;
    const int t0 = blockIdx.x * 32, h0 = blockIdx.y * 32;
    const int x = threadIdx.x, y = threadIdx.y;
#pragma unroll
    for (int i = 0; i < 4; i++)
        t[x][y + 8*i] = g_v[(((long long)(b*S_ + t0 + x)) * NKV_ + kvh) * H_ + h0 + y + 8*i];
    __syncthreads();
    const long long obase = ((long long)z * H_) * S_;
#pragma unroll
    for (int i = 0; i < 4; i++)
        g_vth[obase + (long long)(h0 + y + 8*i) * S_ + t0 + x] = __float2half_rn(t[x][y + 8*i]);
}

// ---------------- RoPE (hi only) ----------------
__global__ void rope_hi_kernel(const float* __restrict__ src,
                               __half* __restrict__ hi, int nheads, float scale)
{
    long long bid = blockIdx.x;
    int t = (int)((bid / nheads) % S_);
    int i = threadIdx.x;
    const float* p = src + bid * H_;
    float x1 = p[i], x2 = p[i + 128];
    float ex = (float)(2*i) * (1.0f / (float)H_);
    float inv_freq = powf(10000.0f, -ex);
    float ff = (float)t * inv_freq;
    double fr = (double)ff;
    const double TWO_PI = 6.283185307179586476925286766559;
    fr = fr - floor(fr / TWO_PI) * TWO_PI;
    float c = cosf((float)fr), s = sinf((float)fr);
    hi[bid*H_ + 2*i]   = __float2half_rn((x1 * c - x2 * s) * scale);
    hi[bid*H_ + 2*i+1] = __float2half_rn((x2 * c + x1 * s) * scale);
}

// ================= plain fp16 GEMM: Ah x Bh, fp32 accum =================
__global__ void __launch_bounds__(256)
hgemm1_kernel(const __half* __restrict__ Ah, int K,
              const __half* __restrict__ Bh,
              long long bZStride, float* __restrict__ C, int ldc, int cZStride)
{
    constexpr uint32_t AHI = 0, BHI = 16384;
    constexpr uint32_t STAGE = 32768u;
    extern __shared__ __half hsm[];
    const uint32_t sb = smem_u32(hsm);

    const int tid = threadIdx.x, wid = tid >> 5, lane = tid & 31;
    const int gid = lane >> 2, tid2 = (lane & 3) * 2;
    const int warpM = wid & 3, warpN = wid >> 2;
    const int lrow = lane & 15, lsel = lane >> 4;

    const int m0 = blockIdx.y * 128, n0 = blockIdx.x * 128, z = blockIdx.z;
    const __half* Bhp = Bh + (long long)z * bZStride;

    float acc[2][8][4];
#pragma unroll
    for (int mt = 0; mt < 2; mt++)
#pragma unroll
        for (int nf = 0; nf < 8; nf++)
#pragma unroll
            for (int r = 0; r < 4; r++) acc[mt][nf][r] = 0.f;

    const int nSlab = K >> 6;

#define FILLG(stage, s) do {                                                  \
    const int k0f = (s) << 6;                                                 \
    const uint32_t stBase = sb + (uint32_t)(stage) * STAGE;                   \
    _Pragma("unroll")                                                         \
    for (int p = 0; p < 4; p++) {                                             \
        const int chunk = p * 256 + tid;                                      \
        const int row = chunk >> 3, c16 = chunk & 7;                          \
        const uint32_t swz = SWZ((uint32_t)(row * 128 + c16 * 16));           \
        const long long ka = (long long)(m0 + row) * K + k0f + c16 * 8;       \
        const long long kb = (long long)(n0 + row) * K + k0f + c16 * 8;       \
        CP16(stBase + AHI + swz, Ah + ka);                                    \
        CP16(stBase + BHI + swz, Bhp + kb);                                   \
    }                                                                         \
    CPCOMMIT();                                                               \
} while (0)

    FILLG(0, 0);
    for (int s = 0; s < nSlab; s++) {
        CPWAIT0();
        __syncthreads();
        if (s + 1 < nSlab) FILLG((s + 1) & 1, s + 1);

        const uint32_t stBase = sb + (uint32_t)(s & 1) * STAGE;
#pragma unroll
        for (int ks = 0; ks < 4; ks++) {
            const int ck = ks * 2 + lsel;
            uint32_t ah[2][4], bh[4][4];
#pragma unroll
            for (int mt = 0; mt < 2; mt++) {
                const int row = warpM * 32 + mt * 16 + lrow;
                LDMX4(ah[mt], stBase + AHI + SWZ((uint32_t)(row * 128 + ck * 16)));
            }
#pragma unroll
            for (int ng = 0; ng < 4; ng++) {
                const int row = warpN * 64 + ng * 16 + lrow;
                LDMX4(bh[ng], stBase + BHI + SWZ((uint32_t)(row * 128 + ck * 16)));
            }
#pragma unroll
            for (int ng = 0; ng < 4; ng++)
#pragma unroll
                for (int h = 0; h < 2; h++) {
                    const int nf = ng * 2 + h;
#pragma unroll
                    for (int mt = 0; mt < 2; mt++)
                        MMA16816(acc[mt][nf], ah[mt], bh[ng][h], bh[ng][2 + h]);
                }
        }
        __syncthreads();
    }
#undef FILLG

#pragma unroll
    for (int mt = 0; mt < 2; mt++) {
        const int row0 = m0 + warpM * 32 + mt * 16 + gid;
#pragma unroll
        for (int nf = 0; nf < 8; nf++) {
            const int col = z * cZStride + n0 + warpN * 64 + nf * 8 + tid2;
            *(float2*)(C + (long long)row0 * ldc + col) =
                make_float2(acc[mt][nf][0], acc[mt][nf][1]);
            *(float2*)(C + (long long)(row0 + 8) * ldc + col) =
                make_float2(acc[mt][nf][2], acc[mt][nf][3]);
        }
    }
}

// ================= tensor-core flash attention (1-term fp16) =================
// q-tile 64, kt-step 32, 256 threads. Q/K natural [t][h]; V pre-transposed [h][t].
// smem rows padded: Q/K 528 B (512 payload), Vt/P 80 B (64 payload).
#define AQH 0u
#define AKH(bf) (33792u + (uint32_t)(bf) * 16896u)
#define AVH 67584u
#define ASS 88064u
#define APH 98304u
#define AMM 103424u
#define ALL 103680u
#define AAL 103936u
#define ATTN_SMEM 104192u

__global__ void __launch_bounds__(256, 1) attn_tc_kernel()
{
    extern __shared__ char smc[];
    const uint32_t sb = smem_u32(smc);
    float*  Ssm = (float*)(smc + ASS);
    __half* Phs = (__half*)(smc + APH);
    float*  Msm = (float*)(smc + AMM);
    float*  Lsm = (float*)(smc + ALL);
    float*  Asm = (float*)(smc + AAL);

    const int tid = threadIdx.x, wid = tid >> 5, lane = tid & 31;
    const int gid = lane >> 2, tid2 = (lane & 3) * 2;
    const int l15 = lane & 15;
    const uint32_t lsel = (uint32_t)(lane >> 4) * 16u;
    const int wrow = (wid & 3) * 16;          // q rows
    const int wkey = (wid >> 2) * 16;         // key cols (QK)
    const int wcol = (wid >> 2) * 128;        // h cols (PV)

    const int qt0 = blockIdx.x * 64;
    const int bn  = blockIdx.y;
    const int b = bn / NQ_, n = bn % NQ_;
    const int kvh = n >> 1;

    if (tid < 64) { Msm[tid] = -1e30f; Lsm[tid] = 0.f; Asm[tid] = 1.f; }

    const size_t qbase  = ((size_t)(b*S_ + qt0) * NQ_ + n) * H_;
    const size_t kbase  = ((size_t)(b*S_) * NKV_ + kvh) * H_;
    const size_t vtbase = ((size_t)(b*NKV_ + kvh)) * H_ * S_;

    // prologue: Q + first K tile
#pragma unroll
    for (int p = 0; p < 8; p++) {
        int chunk = p * 256 + tid;
        int row = chunk >> 5, seg = chunk & 31;
        size_t off = qbase + (size_t)row * (NQ_*H_) + seg * 8;
        CP16(sb + AQH + (uint32_t)(row * 528 + seg * 16), g_qh + off);
    }
    int lo0 = qt0 - (WINDOW_ - 1); if (lo0 < 0) lo0 = 0;
    const int kt_lo = lo0 >> 5;
    const int kt_hi = (qt0 + 63) >> 5;
#pragma unroll
    for (int p = 0; p < 4; p++) {
        int chunk = p * 256 + tid;
        int row = chunk >> 5, seg = chunk & 31;
        size_t off = kbase + (size_t)(kt_lo * 32 + row) * (NKV_*H_) + seg * 8;
        CP16(sb + AKH(0) + (uint32_t)(row * 528 + seg * 16), g_kh + off);
    }
    CPCOMMIT();

    float o[16][4];
#pragma unroll
    for (int nf = 0; nf < 16; nf++)
#pragma unroll
        for (int r = 0; r < 4; r++) o[nf][r] = 0.f;

    for (int kt = kt_lo; kt <= kt_hi; kt++) {
        const int buf = (kt - kt_lo) & 1;
        const int kt0 = kt * 32;
        CPWAIT0();
        __syncthreads();

        // issue V tile for this step
#pragma unroll
        for (int p = 0; p < 4; p++) {
            int chunk = p * 256 + tid;
            int row = chunk >> 2, seg = chunk & 3;
            size_t off = vtbase + (size_t)row * S_ + kt0 + seg * 8;
            CP16(sb + AVH + (uint32_t)(row * 80 + seg * 16), g_vth + off);
        }
        CPCOMMIT();
        // prefetch next K tile
        if (kt < kt_hi) {
#pragma unroll
            for (int p = 0; p < 4; p++) {
                int chunk = p * 256 + tid;
                int row = chunk >> 5, seg = chunk & 31;
                size_t off = kbase + (size_t)(kt0 + 32 + row) * (NKV_*H_) + seg * 8;
                CP16(sb + AKH(buf ^ 1) + (uint32_t)(row * 528 + seg * 16), g_kh + off);
            }
            CPCOMMIT();
        }

        // S = Q Kt (1-term)
        float acc[2][4];
#pragma unroll
        for (int nf = 0; nf < 2; nf++)
#pragma unroll
            for (int r = 0; r < 4; r++) acc[nf][r] = 0.f;
#pragma unroll
        for (int ks = 0; ks < 16; ks++) {
            const uint32_t cb = (uint32_t)(ks * 32) + lsel;
            uint32_t qh4[4], kh4[4];
            LDMX4(qh4, sb + AQH + (uint32_t)((wrow + l15) * 528) + cb);
            LDMX4(kh4, sb + AKH(buf) + (uint32_t)((wkey + l15) * 528) + cb);
#pragma unroll
            for (int nf = 0; nf < 2; nf++)
                MMA16816(acc[nf], qh4, kh4[nf], kh4[2 + nf]);
        }

        // cap + mask, stage S
#pragma unroll
        for (int nf = 0; nf < 2; nf++)
#pragma unroll
            for (int hh = 0; hh < 2; hh++)
#pragma unroll
                for (int jj = 0; jj < 2; jj++) {
                    const int rloc = wrow + gid + hh * 8;
                    const int cloc = wkey + nf * 8 + tid2 + jj;
                    const int tg = qt0 + rloc, sg = kt0 + cloc;
                    float v = acc[nf][hh * 2 + jj];
                    float xv = fminf(fmaxf(v * 0.02f, -15.f), 15.f);
                    float e = __expf(2.f * xv);
                    float lv = 50.f * (e - 1.f) / (e + 1.f);
                    if (sg > tg || sg <= tg - WINDOW_) lv = -1e30f;
                    Ssm[rloc * 40 + cloc] = lv;
                }
        __syncthreads();

        // softmax (thread: row tid>>2, 8 cols)
        {
            const int r = tid >> 2, c0 = (tid & 3) * 8;
            float s[8];
#pragma unroll
            for (int j = 0; j < 8; j++) s[j] = Ssm[r * 40 + c0 + j];
            float mx = s[0];
#pragma unroll
            for (int j = 1; j < 8; j++) mx = fmaxf(mx, s[j]);
            mx = fmaxf(mx, __shfl_xor_sync(0xffffffffu, mx, 1));
            mx = fmaxf(mx, __shfl_xor_sync(0xffffffffu, mx, 2));
            float mold = Msm[r];
            float mnew = fmaxf(mold, mx);
            float alpha = __expf(mold - mnew);
            float ls = 0.f, pv[8];
#pragma unroll
            for (int j = 0; j < 8; j++) {
                pv[j] = (s[j] > -1e29f) ? __expf(s[j] - mnew) : 0.f;
                ls += pv[j];
            }
            ls += __shfl_xor_sync(0xffffffffu, ls, 1);
            ls += __shfl_xor_sync(0xffffffffu, ls, 2);
            if ((tid & 3) == 0) {
                Lsm[r] = Lsm[r] * alpha + ls;
                Msm[r] = mnew;
                Asm[r] = alpha;
            }
#pragma unroll
            for (int j = 0; j < 8; j++)
                Phs[r * 40 + c0 + j] = __float2half_rn(pv[j]);
        }
        if (kt < kt_hi) { CPWAIT1(); } else { CPWAIT0(); }
        __syncthreads();

        // rescale O; O += P V (1-term)
        {
            float a0 = Asm[wrow + gid], a1 = Asm[wrow + gid + 8];
#pragma unroll
            for (int nf = 0; nf < 16; nf++) {
                o[nf][0] *= a0; o[nf][1] *= a0;
                o[nf][2] *= a1; o[nf][3] *= a1;
            }
        }
#pragma unroll
        for (int ks = 0; ks < 2; ks++) {
            const uint32_t cb = (uint32_t)(ks * 32) + lsel;
            uint32_t ph4[4];
            LDMX4(ph4, sb + APH + (uint32_t)((wrow + l15) * 80) + cb);
#pragma unroll
            for (int ng = 0; ng < 8; ng++) {
                uint32_t vh4[4];
                LDMX4(vh4, sb + AVH + (uint32_t)((wcol + ng * 16 + l15) * 80) + cb);
#pragma unroll
                for (int h2 = 0; h2 < 2; h2++)
                    MMA16816(o[ng * 2 + h2], ph4, vh4[h2], vh4[2 + h2]);
            }
        }
    }

    // normalize + write av (fp16)
    {
        float inv0 = 1.f / Lsm[wrow + gid];
        float inv1 = 1.f / Lsm[wrow + gid + 8];
        size_t ob0 = ((size_t)(b*S_ + qt0 + wrow + gid) * NQ_ + n) * H_ + wcol;
        size_t ob1 = ob0 + (size_t)8 * NQ_ * H_;
#pragma unroll
        for (int nf = 0; nf < 16; nf++) {
            size_t c = (size_t)(nf * 8 + tid2);
            *(__half2*)(g_avh + ob0 + c) =
                __halves2half2(__float2half_rn(o[nf][0] * inv0), __float2half_rn(o[nf][1] * inv0));
            *(__half2*)(g_avh + ob1 + c) =
                __halves2half2(__float2half_rn(o[nf][2] * inv1), __float2half_rn(o[nf][3] * inv1));
        }
    }
}

// ---------------- launch ----------------
extern "C" void kernel_launch(void* const* d_in, const int* in_sizes, int n_in,
                              void* d_out, int out_size)
{
    const float* x  = (const float*)d_in[0];
    const float* Wq = (const float*)d_in[1];
    const float* Wk = (const float*)d_in[2];
    const float* Wv = (const float*)d_in[3];
    const float* Wo = (const float*)d_in[4];
    float* out = (float*)d_out;

    float *q, *k, *v;
    cudaGetSymbolAddress((void**)&q, g_q);
    cudaGetSymbolAddress((void**)&k, g_k);
    cudaGetSymbolAddress((void**)&v, g_v);
    __half *xh, *wqh, *wkh, *wvh, *woh, *avh, *qh, *kh;
    cudaGetSymbolAddress((void**)&xh,  g_xh);
    cudaGetSymbolAddress((void**)&wqh, g_wqh);
    cudaGetSymbolAddress((void**)&wkh, g_wkh);
    cudaGetSymbolAddress((void**)&wvh, g_wvh);
    cudaGetSymbolAddress((void**)&woh, g_woh);
    cudaGetSymbolAddress((void**)&avh, g_avh);
    cudaGetSymbolAddress((void**)&qh,  g_qh);
    cudaGetSymbolAddress((void**)&kh,  g_kh);

    const int M = B_ * S_;   // 4096

    cudaFuncSetAttribute(hgemm1_kernel, cudaFuncAttributeMaxDynamicSharedMemorySize, 65536);
    cudaFuncSetAttribute(attn_tc_kernel, cudaFuncAttributeMaxDynamicSharedMemorySize, ATTN_SMEM);

    // conversions
    {
        int n4 = M * D_ / 4;
        convert_hi_kernel<<<(n4 + 255) / 256, 256>>>(x, xh, n4);
    }
    convert_wt_hi_kernel<<<dim3(H_/32, D_/32, NQ_),  dim3(32, 8)>>>(Wq, wqh, D_, H_);
    convert_wt_hi_kernel<<<dim3(H_/32, D_/32, NKV_), dim3(32, 8)>>>(Wk, wkh, D_, H_);
    convert_wt_hi_kernel<<<dim3(H_/32, D_/32, NKV_), dim3(32, 8)>>>(Wv, wvh, D_, H_);
    convert_wt_hi_kernel<<<dim3(D_/32, (NQ_*H_)/32, 1), dim3(32, 8)>>>(Wo, woh, NQ_*H_, D_);

    // QKV projections (1-term fp16)
    hgemm1_kernel<<<dim3(H_/128, M/128, NQ_),  256, 65536>>>(
        xh, D_, wqh, (long long)H_ * D_, q, NQ_*H_, H_);
    hgemm1_kernel<<<dim3(H_/128, M/128, NKV_), 256, 65536>>>(
        xh, D_, wkh, (long long)H_ * D_, k, NKV_*H_, H_);
    hgemm1_kernel<<<dim3(H_/128, M/128, NKV_), 256, 65536>>>(
        xh, D_, wvh, (long long)H_ * D_, v, NKV_*H_, H_);

    // rope, V transpose
    rope_hi_kernel<<<M * NQ_,  128>>>(q, qh, NQ_,  0.0625f);
    rope_hi_kernel<<<M * NKV_, 128>>>(k, kh, NKV_, 1.0f);
    vtrans_kernel<<<dim3(S_/32, H_/32, B_*NKV_), dim3(32, 8)>>>();

    // attention
    attn_tc_kernel<<<dim3(S_/64, B_*NQ_), 256, ATTN_SMEM>>>();

    // output projection (1-term fp16)
    hgemm1_kernel<<<dim3(D_/128, M/128, 1), 256, 65536>>>(
        avh, NQ_*H_, woh, 0, out, D_, 0);
}